// round 1
// baseline (speedup 1.0000x reference)
#include <cuda_runtime.h>
#include <cstddef>

// Problem dims
#define BB   8
#define CC   256
#define CHI  128
#define HH   64
#define WW   64
#define NPIX 4096   // H*W
#define MPOOL 1024  // (H/2)*(W/2)

// ---------------- device scratch (no allocations allowed) ----------------
__device__ float g_pq[BB * CC * MPOOL];                 // pooled q  [b][c][m]
__device__ float g_pv[BB * CC * MPOOL];                 // pooled v  [b][c][m]
__device__ float g_theta[(size_t)BB * NPIX * CHI];      // [b][n][ci]
__device__ float g_phi[BB * MPOOL * CHI];               // [b][m][ci]
__device__ float g_gm[BB * MPOOL * CHI];                // [b][m][ci]
__device__ float g_f[(size_t)BB * NPIX * MPOOL];        // [b][n][m]  (scores -> probs)
__device__ float g_y[(size_t)BB * NPIX * CHI];          // [b][n][ci]
__device__ float g_bns[CC];                             // BN scale per out-channel
__device__ float g_bnt[CC];                             // BN shift (incl conv bias) per out-channel

// ---------------- pooling: 2x2 average of q and v ----------------
__global__ void pool_kernel(const float* __restrict__ q, const float* __restrict__ v) {
    int idx = blockIdx.x * blockDim.x + threadIdx.x;
    const int total = BB * CC * MPOOL;
    if (idx >= 2 * total) return;
    const float* src = (idx < total) ? q : v;
    float* dst = (idx < total) ? g_pq : g_pv;
    int i = (idx < total) ? idx : idx - total;
    int m = i & (MPOOL - 1);
    int bc = i >> 10;               // i / MPOOL
    int mi = m >> 5, mj = m & 31;
    const float* p = src + ((size_t)bc * HH + 2 * mi) * WW + 2 * mj;
    dst[i] = 0.25f * (p[0] + p[1] + p[WW] + p[WW + 1]);
}

// ---------------- BN constant precompute ----------------
__global__ void bn_kernel(const float* __restrict__ gamma, const float* __restrict__ beta,
                          const float* __restrict__ mean, const float* __restrict__ var,
                          const float* __restrict__ bw) {
    int o = threadIdx.x;
    float s = gamma[o] * rsqrtf(var[o] + 1e-5f);
    g_bns[o] = s;
    g_bnt[o] = beta[o] + (bw[o] - mean[o]) * s;
}

// ---------------- generic 128x128x8 SGEMM, 8x8 micro-tiles ----------------
// A_KM:  A stored [K][M] (m contiguous, leading dim lda)  else [M][K] (k contiguous)
// B_KN:  B stored [K][N] (n contiguous, leading dim ldb)  else [N][K] (k contiguous)
// EPI 0: C = acc
// EPI 1: C = acc + bias[col]
// EPI 2: C = acc * g_bns[row] + g_bnt[row] + resid[row*ldc + col]   (final BN + residual)
template <bool A_KM, bool B_KN, int EPI>
__global__ __launch_bounds__(256) void gemm128(
    const float* __restrict__ A, const float* __restrict__ B, float* __restrict__ C,
    int K, int lda, int ldb, int ldc,
    size_t strideA, size_t strideB, size_t strideC,
    const float* __restrict__ bias,
    const float* __restrict__ resid, size_t strideR) {
    __shared__ float As[8][128];
    __shared__ float Bs[8][128];

    int b = blockIdx.z;
    A += strideA * b;
    B += strideB * b;
    C += strideC * b;
    if (EPI == 2) resid += strideR * b;

    int m0 = blockIdx.y * 128;
    int n0 = blockIdx.x * 128;
    int tid = threadIdx.x;
    int tx = tid & 15, ty = tid >> 4;

    float acc[8][8];
#pragma unroll
    for (int i = 0; i < 8; i++)
#pragma unroll
        for (int j = 0; j < 8; j++) acc[i][j] = 0.f;

    for (int k0 = 0; k0 < K; k0 += 8) {
        if (A_KM) {
            int r = tid >> 5, c = (tid & 31) * 4;
            *(float4*)&As[r][c] = *(const float4*)(A + (size_t)(k0 + r) * lda + m0 + c);
        } else {
            int m = tid >> 1, h = (tid & 1) * 4;
            float4 va = *(const float4*)(A + (size_t)(m0 + m) * lda + k0 + h);
            As[h + 0][m] = va.x; As[h + 1][m] = va.y; As[h + 2][m] = va.z; As[h + 3][m] = va.w;
        }
        if (B_KN) {
            int r = tid >> 5, c = (tid & 31) * 4;
            *(float4*)&Bs[r][c] = *(const float4*)(B + (size_t)(k0 + r) * ldb + n0 + c);
        } else {
            int n = tid >> 1, h = (tid & 1) * 4;
            float4 vb = *(const float4*)(B + (size_t)(n0 + n) * ldb + k0 + h);
            Bs[h + 0][n] = vb.x; Bs[h + 1][n] = vb.y; Bs[h + 2][n] = vb.z; Bs[h + 3][n] = vb.w;
        }
        __syncthreads();
#pragma unroll
        for (int kk = 0; kk < 8; kk++) {
            float af[8], bf[8];
            *(float4*)af       = *(float4*)&As[kk][ty * 4];
            *(float4*)(af + 4) = *(float4*)&As[kk][64 + ty * 4];
            *(float4*)bf       = *(float4*)&Bs[kk][tx * 4];
            *(float4*)(bf + 4) = *(float4*)&Bs[kk][64 + tx * 4];
#pragma unroll
            for (int i = 0; i < 8; i++)
#pragma unroll
                for (int j = 0; j < 8; j++) acc[i][j] += af[i] * bf[j];
        }
        __syncthreads();
    }

#pragma unroll
    for (int i = 0; i < 8; i++) {
        int m = m0 + ((i < 4) ? (ty * 4 + i) : (64 + ty * 4 + i - 4));
        float scale = 1.f, shift = 0.f;
        if (EPI == 2) { scale = g_bns[m]; shift = g_bnt[m]; }
#pragma unroll
        for (int jh = 0; jh < 2; jh++) {
            int n = n0 + jh * 64 + tx * 4;
            float4 o;
            float a0 = acc[i][jh * 4 + 0], a1 = acc[i][jh * 4 + 1];
            float a2 = acc[i][jh * 4 + 2], a3 = acc[i][jh * 4 + 3];
            if (EPI == 0) {
                o = make_float4(a0, a1, a2, a3);
            } else if (EPI == 1) {
                o = make_float4(a0 + bias[n], a1 + bias[n + 1], a2 + bias[n + 2], a3 + bias[n + 3]);
            } else {
                const float* rp = resid + (size_t)m * ldc + n;
                o = make_float4(a0 * scale + shift + rp[0],
                                a1 * scale + shift + rp[1],
                                a2 * scale + shift + rp[2],
                                a3 * scale + shift + rp[3]);
            }
            *(float4*)(C + (size_t)m * ldc + n) = o;
        }
    }
}

// ---------------- row softmax over M=1024 ----------------
__global__ __launch_bounds__(256) void softmax_kernel(float* __restrict__ f) {
    float* row = f + ((size_t)blockIdx.y * NPIX + blockIdx.x) * MPOOL;
    int tid = threadIdx.x;
    float4 vv = *(float4*)(row + tid * 4);
    float mx = fmaxf(fmaxf(vv.x, vv.y), fmaxf(vv.z, vv.w));
#pragma unroll
    for (int o = 16; o; o >>= 1) mx = fmaxf(mx, __shfl_xor_sync(0xffffffffu, mx, o));
    __shared__ float redm[8];
    __shared__ float reds[8];
    if ((tid & 31) == 0) redm[tid >> 5] = mx;
    __syncthreads();
    mx = redm[0];
#pragma unroll
    for (int i = 1; i < 8; i++) mx = fmaxf(mx, redm[i]);
    vv.x = __expf(vv.x - mx);
    vv.y = __expf(vv.y - mx);
    vv.z = __expf(vv.z - mx);
    vv.w = __expf(vv.w - mx);
    float s = vv.x + vv.y + vv.z + vv.w;
#pragma unroll
    for (int o = 16; o; o >>= 1) s += __shfl_xor_sync(0xffffffffu, s, o);
    if ((tid & 31) == 0) reds[tid >> 5] = s;
    __syncthreads();
    float tot = reds[0];
#pragma unroll
    for (int i = 1; i < 8; i++) tot += reds[i];
    float inv = 1.f / tot;
    vv.x *= inv; vv.y *= inv; vv.z *= inv; vv.w *= inv;
    *(float4*)(row + tid * 4) = vv;
}

// ---------------- launch ----------------
extern "C" void kernel_launch(void* const* d_in, const int* in_sizes, int n_in,
                              void* d_out, int out_size) {
    (void)in_sizes; (void)n_in; (void)out_size;
    const float* q     = (const float*)d_in[0];
    const float* k     = (const float*)d_in[1];
    const float* v     = (const float*)d_in[2];
    const float* Wg    = (const float*)d_in[3];
    const float* bg    = (const float*)d_in[4];
    const float* Wth   = (const float*)d_in[5];
    const float* bth   = (const float*)d_in[6];
    const float* Wph   = (const float*)d_in[7];
    const float* bph   = (const float*)d_in[8];
    const float* Ww    = (const float*)d_in[9];
    const float* bw    = (const float*)d_in[10];
    const float* gamma = (const float*)d_in[11];
    const float* beta  = (const float*)d_in[12];
    const float* mean  = (const float*)d_in[13];
    const float* var   = (const float*)d_in[14];
    float* out = (float*)d_out;

    float *pq, *pv, *theta, *phi, *gm, *f, *y;
    cudaGetSymbolAddress((void**)&pq, g_pq);
    cudaGetSymbolAddress((void**)&pv, g_pv);
    cudaGetSymbolAddress((void**)&theta, g_theta);
    cudaGetSymbolAddress((void**)&phi, g_phi);
    cudaGetSymbolAddress((void**)&gm, g_gm);
    cudaGetSymbolAddress((void**)&f, g_f);
    cudaGetSymbolAddress((void**)&y, g_y);

    // 1) 2x2 avg pool of q and v (pool commutes with 1x1 conv)
    {
        int total = 2 * BB * CC * MPOOL;
        pool_kernel<<<(total + 255) / 256, 256>>>(q, v);
    }
    // 2) BN constants
    bn_kernel<<<1, CC>>>(gamma, beta, mean, var, bw);

    // 3) theta = conv1x1(k, Wth) -> [b][n][ci]   (A = k [C][N] direct, B = Wth [CI][C] transp)
    {
        dim3 grid(CHI / 128, NPIX / 128, BB);
        gemm128<true, false, 1><<<grid, 256>>>(k, Wth, theta, CC, NPIX, CC, CHI,
                                               (size_t)CC * NPIX, 0, (size_t)NPIX * CHI,
                                               bth, nullptr, 0);
    }
    // 4) phi = conv1x1(pooled q, Wph) -> [b][m][ci]
    {
        dim3 grid(CHI / 128, MPOOL / 128, BB);
        gemm128<true, false, 1><<<grid, 256>>>(pq, Wph, phi, CC, MPOOL, CC, CHI,
                                               (size_t)CC * MPOOL, 0, (size_t)MPOOL * CHI,
                                               bph, nullptr, 0);
        // 5) g = conv1x1(pooled v, Wg) -> [b][m][ci]
        gemm128<true, false, 1><<<grid, 256>>>(pv, Wg, gm, CC, MPOOL, CC, CHI,
                                               (size_t)CC * MPOOL, 0, (size_t)MPOOL * CHI,
                                               bg, nullptr, 0);
    }
    // 6) f[n][m] = theta[n][:] . phi[m][:]   (A rowmajor [N][CI], B rowmajor [M][CI] transp)
    {
        dim3 grid(MPOOL / 128, NPIX / 128, BB);
        gemm128<false, false, 0><<<grid, 256>>>(theta, phi, f, CHI, CHI, CHI, MPOOL,
                                                (size_t)NPIX * CHI, (size_t)MPOOL * CHI,
                                                (size_t)NPIX * MPOOL, nullptr, nullptr, 0);
    }
    // 7) softmax over m
    {
        dim3 grid(NPIX, BB);
        softmax_kernel<<<grid, 256>>>(f);
    }
    // 8) y[n][ci] = P[n][:] . g[:][ci]   (A rowmajor [N][M], B = g [M][CI] direct)
    {
        dim3 grid(CHI / 128, NPIX / 128, BB);
        gemm128<false, true, 0><<<grid, 256>>>(f, gm, y, MPOOL, MPOOL, CHI, CHI,
                                               (size_t)NPIX * MPOOL, (size_t)MPOOL * CHI,
                                               (size_t)NPIX * CHI, nullptr, nullptr, 0);
    }
    // 9) out[o][n] = BN(Ww[o][:] . y[n][:]) + v[o][n]
    {
        dim3 grid(NPIX / 128, CC / 128, BB);
        gemm128<false, false, 2><<<grid, 256>>>(Ww, y, out, CHI, CHI, CHI, NPIX,
                                                0, (size_t)NPIX * CHI, (size_t)CC * NPIX,
                                                nullptr, v, (size_t)CC * NPIX);
    }
}

// round 3
// speedup vs baseline: 2.3071x; 2.3071x over previous
#include <cuda_runtime.h>
#include <cuda_fp16.h>
#include <cstdint>
#include <cstddef>

// Problem dims
#define BB   8
#define CC   256
#define CHI  128
#define HH   64
#define WW   64
#define NPIX 4096   // H*W
#define MPOOL 1024  // (H/2)*(W/2)

// ---------------- device scratch (no allocations allowed) ----------------
__device__ __half h_kT_hi[(size_t)BB * NPIX * CC];
__device__ __half h_kT_lo[(size_t)BB * NPIX * CC];
__device__ __half h_pq_hi[BB * MPOOL * CC];
__device__ __half h_pq_lo[BB * MPOOL * CC];
__device__ __half h_pv_hi[BB * MPOOL * CC];
__device__ __half h_Wth_hi[CHI * CC];
__device__ __half h_Wth_lo[CHI * CC];
__device__ __half h_Wph_hi[CHI * CC];
__device__ __half h_Wph_lo[CHI * CC];
__device__ __half h_Wg_hi[CHI * CC];
__device__ __half h_Ww_hi[CC * CHI];
__device__ __half h_th_hi[(size_t)BB * NPIX * CHI];
__device__ __half h_th_lo[(size_t)BB * NPIX * CHI];
__device__ __half h_ph_hi[BB * MPOOL * CHI];
__device__ __half h_ph_lo[BB * MPOOL * CHI];
__device__ __half h_g[BB * CHI * MPOOL];
__device__ float  g_f[(size_t)BB * NPIX * MPOOL];
__device__ __half h_P[(size_t)BB * NPIX * MPOOL];
__device__ __half h_y[(size_t)BB * NPIX * CHI];
__device__ float  g_bns[CC];
__device__ float  g_bnt[CC];

// ---------------- PTX helpers (all base-target, sm_80-level) ----------------
__device__ __forceinline__ uint32_t smem_u32(const void* p) {
    uint32_t a;
    asm("{ .reg .u64 t; cvta.to.shared.u64 t, %1; cvt.u32.u64 %0, t; }" : "=r"(a) : "l"(p));
    return a;
}
__device__ __forceinline__ void cp16(uint32_t d, const void* s) {
    asm volatile("cp.async.cg.shared.global [%0], [%1], 16;" :: "r"(d), "l"(s) : "memory");
}
__device__ __forceinline__ void cp_commit() {
    asm volatile("cp.async.commit_group;" ::: "memory");
}
template <int N>
__device__ __forceinline__ void cp_wait() {
    asm volatile("cp.async.wait_group %0;" :: "n"(N) : "memory");
}
__device__ __forceinline__ void ldsm4(uint32_t& r0, uint32_t& r1, uint32_t& r2, uint32_t& r3,
                                      uint32_t a) {
    asm volatile("ldmatrix.sync.aligned.m8n8.x4.shared.b16 {%0,%1,%2,%3}, [%4];"
                 : "=r"(r0), "=r"(r1), "=r"(r2), "=r"(r3) : "r"(a));
}
__device__ __forceinline__ void mma16816(float* c, const uint32_t* a, const uint32_t* b) {
    asm volatile(
        "mma.sync.aligned.m16n8k16.row.col.f32.f16.f16.f32 "
        "{%0,%1,%2,%3}, {%4,%5,%6,%7}, {%8,%9}, {%0,%1,%2,%3};"
        : "+f"(c[0]), "+f"(c[1]), "+f"(c[2]), "+f"(c[3])
        : "r"(a[0]), "r"(a[1]), "r"(a[2]), "r"(a[3]), "r"(b[0]), "r"(b[1]));
}

// ---------------- unified fp16 tensor-core GEMM ----------------
// C[row][col] = sum_k A[row][k] * B[col][k]; both operands K-major fp16.
// Block tile 128x128, warp tile 64x32, k-chunk 32, double-buffered cp.async.
// SPLIT: A,B have lo parts; acc += Ahi*Bhi + Ahi*Blo + Alo*Bhi.
// EPI 0: fp32 store | 1: +bias[col], split hi/lo fp16 store | 2: +bias[row], fp16
//     3: fp16 store | 4: *bns[row]+bnt[row]+resid, fp32 store
template <int K_TOTAL, bool SPLIT, int EPI>
__global__ void __launch_bounds__(256, 1) hgemm(
    const __half* __restrict__ Ahi, const __half* __restrict__ Alo,
    const __half* __restrict__ Bhi, const __half* __restrict__ Blo,
    float* __restrict__ Cf, __half* __restrict__ Ch, __half* __restrict__ Cl,
    size_t aB, size_t bB, size_t cB, int ldc,
    const float* __restrict__ bias,
    const float* __restrict__ resid, size_t rB, int ldr) {
    constexpr int NCH = K_TOTAL / 32;
    constexpr int STAGE = SPLIT ? 40960 : 20480;
    extern __shared__ char sm[];
    uint32_t sbase = smem_u32(sm);

    int tid = threadIdx.x, lane = tid & 31, w = tid >> 5;
    int wm = w >> 2, wn = w & 3;
    int z = blockIdx.z;

    const __half* Ag = Ahi + aB * z + (size_t)blockIdx.y * 128 * K_TOTAL;
    const __half* Bg = Bhi + bB * z + (size_t)blockIdx.x * 128 * K_TOTAL;
    const __half* Agl = SPLIT ? (Alo + aB * z + (size_t)blockIdx.y * 128 * K_TOTAL) : nullptr;
    const __half* Bgl = SPLIT ? (Blo + bB * z + (size_t)blockIdx.x * 128 * K_TOTAL) : nullptr;

    auto load_chunk = [&](int ch) {
        uint32_t st = sbase + (uint32_t)(ch & 1) * STAGE;
        int k0 = ch * 32;
#pragma unroll
        for (int t = 0; t < 2; t++) {
            int c = tid + t * 256;
            int row = c >> 2, j = c & 3;
            uint32_t d = st + row * 80 + j * 16;
            size_t go = (size_t)row * K_TOTAL + k0 + j * 8;
            cp16(d, Ag + go);
            cp16(d + 10240, Bg + go);
            if (SPLIT) {
                cp16(d + 20480, Agl + go);
                cp16(d + 30720, Bgl + go);
            }
        }
        cp_commit();
    };

    float acc[4][4][4];
#pragma unroll
    for (int i = 0; i < 4; i++)
#pragma unroll
        for (int j = 0; j < 4; j++)
#pragma unroll
            for (int e = 0; e < 4; e++) acc[i][j][e] = 0.f;

    load_chunk(0);

    for (int ch = 0; ch < NCH; ch++) {
        if (ch + 1 < NCH) {
            load_chunk(ch + 1);
            cp_wait<1>();
        } else {
            cp_wait<0>();
        }
        __syncthreads();
        uint32_t sa = sbase + (uint32_t)(ch & 1) * STAGE;
        uint32_t sb = sa + 10240;
#pragma unroll
        for (int k16 = 0; k16 < 2; k16++) {
            uint32_t a[4][4], b[4][2];
            uint32_t coff = (uint32_t)(k16 * 32 + (lane >> 4) * 16);
#pragma unroll
            for (int mi = 0; mi < 4; mi++) {
                uint32_t ad = sa + (uint32_t)(wm * 64 + mi * 16 + (lane & 15)) * 80 + coff;
                ldsm4(a[mi][0], a[mi][1], a[mi][2], a[mi][3], ad);
            }
#pragma unroll
            for (int nh = 0; nh < 2; nh++) {
                uint32_t bd = sb + (uint32_t)(wn * 32 + nh * 16 + (lane & 15)) * 80 + coff;
                uint32_t r0, r1, r2, r3;
                ldsm4(r0, r1, r2, r3, bd);
                b[nh * 2 + 0][0] = r0; b[nh * 2 + 0][1] = r2;
                b[nh * 2 + 1][0] = r1; b[nh * 2 + 1][1] = r3;
            }
#pragma unroll
            for (int mi = 0; mi < 4; mi++)
#pragma unroll
                for (int ni = 0; ni < 4; ni++) mma16816(acc[mi][ni], a[mi], b[ni]);
            if (SPLIT) {
                uint32_t al[4][4], bl[4][2];
#pragma unroll
                for (int mi = 0; mi < 4; mi++) {
                    uint32_t ad = sa + 20480 + (uint32_t)(wm * 64 + mi * 16 + (lane & 15)) * 80 + coff;
                    ldsm4(al[mi][0], al[mi][1], al[mi][2], al[mi][3], ad);
                }
#pragma unroll
                for (int nh = 0; nh < 2; nh++) {
                    uint32_t bd = sa + 30720 + (uint32_t)(wn * 32 + nh * 16 + (lane & 15)) * 80 + coff;
                    uint32_t r0, r1, r2, r3;
                    ldsm4(r0, r1, r2, r3, bd);
                    bl[nh * 2 + 0][0] = r0; bl[nh * 2 + 0][1] = r2;
                    bl[nh * 2 + 1][0] = r1; bl[nh * 2 + 1][1] = r3;
                }
#pragma unroll
                for (int mi = 0; mi < 4; mi++)
#pragma unroll
                    for (int ni = 0; ni < 4; ni++) {
                        mma16816(acc[mi][ni], a[mi], bl[ni]);
                        mma16816(acc[mi][ni], al[mi], b[ni]);
                    }
            }
        }
        __syncthreads();
    }

    // ---------------- epilogue ----------------
    int r = lane >> 2, cp2 = (lane & 3) * 2;
    int row0 = blockIdx.y * 128 + wm * 64;
    int col0 = blockIdx.x * 128 + wn * 32;
    float* Cfz = (EPI == 0 || EPI == 4) ? Cf + cB * z : nullptr;
    __half* Chz = (EPI == 1 || EPI == 2 || EPI == 3) ? Ch + cB * z : nullptr;
    __half* Clz = (EPI == 1) ? Cl + cB * z : nullptr;
    const float* Rz = (EPI == 4) ? resid + rB * z : nullptr;

#pragma unroll
    for (int mi = 0; mi < 4; mi++) {
#pragma unroll
        for (int h = 0; h < 2; h++) {
            int row = row0 + mi * 16 + h * 8 + r;
            float s = 1.f, t = 0.f;
            if (EPI == 2) t = bias[row];
            if (EPI == 4) { s = g_bns[row]; t = g_bnt[row]; }
#pragma unroll
            for (int ni = 0; ni < 4; ni++) {
                int col = col0 + ni * 8 + cp2;
                float v0 = acc[mi][ni][h * 2 + 0];
                float v1 = acc[mi][ni][h * 2 + 1];
                if (EPI == 0) {
                    *(float2*)(Cfz + (size_t)row * ldc + col) = make_float2(v0, v1);
                } else if (EPI == 1) {
                    v0 += bias[col]; v1 += bias[col + 1];
                    __half h0 = __float2half_rn(v0), h1 = __float2half_rn(v1);
                    *(__half2*)(Chz + (size_t)row * ldc + col) = __halves2half2(h0, h1);
                    __half l0 = __float2half_rn(v0 - __half2float(h0));
                    __half l1 = __float2half_rn(v1 - __half2float(h1));
                    *(__half2*)(Clz + (size_t)row * ldc + col) = __halves2half2(l0, l1);
                } else if (EPI == 2 || EPI == 3) {
                    float u0 = v0 + t, u1 = v1 + t;
                    *(__half2*)(Chz + (size_t)row * ldc + col) =
                        __halves2half2(__float2half_rn(u0), __float2half_rn(u1));
                } else {
                    float2 rr = *(const float2*)(Rz + (size_t)row * ldr + col);
                    *(float2*)(Cfz + (size_t)row * ldc + col) =
                        make_float2(v0 * s + t + rr.x, v1 * s + t + rr.y);
                }
            }
        }
    }
}

// ---------------- weight prep: fp32 -> fp16 hi/lo + BN constants ----------------
__global__ void wprep_kernel(const float* __restrict__ Wth, const float* __restrict__ Wph,
                             const float* __restrict__ Wg, const float* __restrict__ Ww,
                             const float* __restrict__ gamma, const float* __restrict__ beta,
                             const float* __restrict__ mean, const float* __restrict__ var,
                             const float* __restrict__ bw) {
    int i = blockIdx.x * 256 + threadIdx.x;  // 0..32767
    float a = Wth[i];
    __half h = __float2half_rn(a);
    h_Wth_hi[i] = h;
    h_Wth_lo[i] = __float2half_rn(a - __half2float(h));
    float b = Wph[i];
    __half hb = __float2half_rn(b);
    h_Wph_hi[i] = hb;
    h_Wph_lo[i] = __float2half_rn(b - __half2float(hb));
    h_Wg_hi[i] = __float2half_rn(Wg[i]);
    h_Ww_hi[i] = __float2half_rn(Ww[i]);
    if (i < CC) {
        float sc = gamma[i] * rsqrtf(var[i] + 1e-5f);
        g_bns[i] = sc;
        g_bnt[i] = beta[i] + (bw[i] - mean[i]) * sc;
    }
}

// ---------------- pool(2x2) + transpose -> fp16 [m][c] (q split, v hi) ----------------
__global__ void __launch_bounds__(256) pooltrans_kernel(const float* __restrict__ q,
                                                        const float* __restrict__ v) {
    __shared__ float ts[32][33];
    int z = blockIdx.z;
    bool isq = (z < BB);
    const float* src = isq ? q : v;
    int b = z & (BB - 1);
    int m0 = blockIdx.x * 32, c0 = blockIdx.y * 32;
    int tx = threadIdx.x, ty = threadIdx.y;
    const float* sb = src + (size_t)b * CC * NPIX;
    int m = m0 + tx, mi = m >> 5, mj = m & 31;
#pragma unroll
    for (int i = 0; i < 4; i++) {
        int c = c0 + ty + i * 8;
        const float* p = sb + (size_t)c * NPIX + (2 * mi) * WW + 2 * mj;
        ts[ty + i * 8][tx] = 0.25f * (p[0] + p[1] + p[WW] + p[WW + 1]);
    }
    __syncthreads();
    size_t base = (size_t)b * MPOOL * CC;
#pragma unroll
    for (int i = 0; i < 4; i++) {
        float val = ts[tx][ty + i * 8];
        size_t idx = base + (size_t)(m0 + ty + i * 8) * CC + c0 + tx;
        __half h = __float2half_rn(val);
        if (isq) {
            h_pq_hi[idx] = h;
            h_pq_lo[idx] = __float2half_rn(val - __half2float(h));
        } else {
            h_pv_hi[idx] = h;
        }
    }
}

// ---------------- transpose k: [c][n] -> fp16 hi/lo [n][c] ----------------
__global__ void __launch_bounds__(256) transk_kernel(const float* __restrict__ k) {
    __shared__ float ts[32][33];
    int b = blockIdx.z;
    int n0 = blockIdx.x * 32, c0 = blockIdx.y * 32;
    int tx = threadIdx.x, ty = threadIdx.y;
    const float* sb = k + (size_t)b * CC * NPIX;
#pragma unroll
    for (int i = 0; i < 4; i++)
        ts[ty + i * 8][tx] = sb[(size_t)(c0 + ty + i * 8) * NPIX + n0 + tx];
    __syncthreads();
    size_t base = (size_t)b * NPIX * CC;
#pragma unroll
    for (int i = 0; i < 4; i++) {
        float val = ts[tx][ty + i * 8];
        size_t idx = base + (size_t)(n0 + ty + i * 8) * CC + c0 + tx;
        __half h = __float2half_rn(val);
        h_kT_hi[idx] = h;
        h_kT_lo[idx] = __float2half_rn(val - __half2float(h));
    }
}

// ---------------- row softmax over M=1024: fp32 logits -> fp16 probs ----------------
__global__ void __launch_bounds__(256) softmax_kernel(const float* __restrict__ f,
                                                      __half* __restrict__ P) {
    size_t ro = ((size_t)blockIdx.y * NPIX + blockIdx.x) * MPOOL;
    const float* row = f + ro;
    __half* prow = P + ro;
    int tid = threadIdx.x;
    float4 vv = *(const float4*)(row + tid * 4);
    float mx = fmaxf(fmaxf(vv.x, vv.y), fmaxf(vv.z, vv.w));
#pragma unroll
    for (int o = 16; o; o >>= 1) mx = fmaxf(mx, __shfl_xor_sync(0xffffffffu, mx, o));
    __shared__ float redm[8];
    __shared__ float reds[8];
    if ((tid & 31) == 0) redm[tid >> 5] = mx;
    __syncthreads();
    mx = redm[0];
#pragma unroll
    for (int i = 1; i < 8; i++) mx = fmaxf(mx, redm[i]);
    vv.x = __expf(vv.x - mx); vv.y = __expf(vv.y - mx);
    vv.z = __expf(vv.z - mx); vv.w = __expf(vv.w - mx);
    float ssum = vv.x + vv.y + vv.z + vv.w;
#pragma unroll
    for (int o = 16; o; o >>= 1) ssum += __shfl_xor_sync(0xffffffffu, ssum, o);
    if ((tid & 31) == 0) reds[tid >> 5] = ssum;
    __syncthreads();
    float tot = reds[0];
#pragma unroll
    for (int i = 1; i < 8; i++) tot += reds[i];
    float inv = 1.f / tot;
    *(__half2*)(prow + tid * 4)     = __floats2half2_rn(vv.x * inv, vv.y * inv);
    *(__half2*)(prow + tid * 4 + 2) = __floats2half2_rn(vv.z * inv, vv.w * inv);
}

// ---------------- launch ----------------
extern "C" void kernel_launch(void* const* d_in, const int* in_sizes, int n_in,
                              void* d_out, int out_size) {
    (void)in_sizes; (void)n_in; (void)out_size;
    const float* q     = (const float*)d_in[0];
    const float* k     = (const float*)d_in[1];
    const float* v     = (const float*)d_in[2];
    const float* Wg    = (const float*)d_in[3];
    const float* bg    = (const float*)d_in[4];
    const float* Wth   = (const float*)d_in[5];
    const float* bth   = (const float*)d_in[6];
    const float* Wph   = (const float*)d_in[7];
    const float* bph   = (const float*)d_in[8];
    const float* Ww    = (const float*)d_in[9];
    const float* bw    = (const float*)d_in[10];
    const float* gamma = (const float*)d_in[11];
    const float* beta  = (const float*)d_in[12];
    const float* mean  = (const float*)d_in[13];
    const float* var   = (const float*)d_in[14];
    float* out = (float*)d_out;

    __half *kThi, *kTlo, *pqhi, *pqlo, *pvhi;
    __half *Wthhi, *Wthlo, *Wphhi, *Wphlo, *Wghi, *Wwhi;
    __half *thhi, *thlo, *phhi, *phlo, *gmat, *P, *y;
    float *f;
    cudaGetSymbolAddress((void**)&kThi, h_kT_hi);
    cudaGetSymbolAddress((void**)&kTlo, h_kT_lo);
    cudaGetSymbolAddress((void**)&pqhi, h_pq_hi);
    cudaGetSymbolAddress((void**)&pqlo, h_pq_lo);
    cudaGetSymbolAddress((void**)&pvhi, h_pv_hi);
    cudaGetSymbolAddress((void**)&Wthhi, h_Wth_hi);
    cudaGetSymbolAddress((void**)&Wthlo, h_Wth_lo);
    cudaGetSymbolAddress((void**)&Wphhi, h_Wph_hi);
    cudaGetSymbolAddress((void**)&Wphlo, h_Wph_lo);
    cudaGetSymbolAddress((void**)&Wghi, h_Wg_hi);
    cudaGetSymbolAddress((void**)&Wwhi, h_Ww_hi);
    cudaGetSymbolAddress((void**)&thhi, h_th_hi);
    cudaGetSymbolAddress((void**)&thlo, h_th_lo);
    cudaGetSymbolAddress((void**)&phhi, h_ph_hi);
    cudaGetSymbolAddress((void**)&phlo, h_ph_lo);
    cudaGetSymbolAddress((void**)&gmat, h_g);
    cudaGetSymbolAddress((void**)&f, g_f);
    cudaGetSymbolAddress((void**)&P, h_P);
    cudaGetSymbolAddress((void**)&y, h_y);

    const int SMS = 81920;  // split: 2 stages x 40KB
    const int SMN = 40960;  // plain: 2 stages x 20KB
    cudaFuncSetAttribute(hgemm<256, true, 1>, cudaFuncAttributeMaxDynamicSharedMemorySize, SMS);
    cudaFuncSetAttribute(hgemm<128, true, 0>, cudaFuncAttributeMaxDynamicSharedMemorySize, SMS);
    cudaFuncSetAttribute(hgemm<256, false, 2>, cudaFuncAttributeMaxDynamicSharedMemorySize, SMN);
    cudaFuncSetAttribute(hgemm<1024, false, 3>, cudaFuncAttributeMaxDynamicSharedMemorySize, SMN);
    cudaFuncSetAttribute(hgemm<128, false, 4>, cudaFuncAttributeMaxDynamicSharedMemorySize, SMN);

    // 1) prep
    wprep_kernel<<<CHI * CC / 256, 256>>>(Wth, Wph, Wg, Ww, gamma, beta, mean, var, bw);
    pooltrans_kernel<<<dim3(MPOOL / 32, CC / 32, 2 * BB), dim3(32, 8)>>>(q, v);
    transk_kernel<<<dim3(NPIX / 32, CC / 32, BB), dim3(32, 8)>>>(k);

    // 2) theta[n][ci] = kT[n][c] . Wth[ci][c]  (split, +bth, split-write)
    hgemm<256, true, 1><<<dim3(1, NPIX / 128, BB), 256, SMS>>>(
        kThi, kTlo, Wthhi, Wthlo, nullptr, thhi, thlo,
        (size_t)NPIX * CC, 0, (size_t)NPIX * CHI, CHI, bth, nullptr, 0, 0);
    // 3) phi[m][ci] = pq[m][c] . Wph[ci][c]
    hgemm<256, true, 1><<<dim3(1, MPOOL / 128, BB), 256, SMS>>>(
        pqhi, pqlo, Wphhi, Wphlo, nullptr, phhi, phlo,
        (size_t)MPOOL * CC, 0, (size_t)MPOOL * CHI, CHI, bph, nullptr, 0, 0);
    // 4) g[ci][m] = Wg[ci][c] . pv[m][c]  (+bg[row], fp16)
    hgemm<256, false, 2><<<dim3(MPOOL / 128, 1, BB), 256, SMN>>>(
        Wghi, nullptr, pvhi, nullptr, nullptr, gmat, nullptr,
        0, (size_t)MPOOL * CC, (size_t)CHI * MPOOL, MPOOL, bg, nullptr, 0, 0);
    // 5) f[n][m] = theta[n][ci] . phi[m][ci]  (split, fp32 logits)
    hgemm<128, true, 0><<<dim3(MPOOL / 128, NPIX / 128, BB), 256, SMS>>>(
        thhi, thlo, phhi, phlo, f, nullptr, nullptr,
        (size_t)NPIX * CHI, (size_t)MPOOL * CHI, (size_t)NPIX * MPOOL, MPOOL,
        nullptr, nullptr, 0, 0);
    // 6) softmax -> fp16 probs
    softmax_kernel<<<dim3(NPIX, BB), 256>>>(f, P);
    // 7) y[n][ci] = P[n][m] . g[ci][m]  (fp16)
    hgemm<1024, false, 3><<<dim3(1, NPIX / 128, BB), 256, SMN>>>(
        P, nullptr, gmat, nullptr, nullptr, y, nullptr,
        (size_t)NPIX * MPOOL, (size_t)CHI * MPOOL, (size_t)NPIX * CHI, CHI,
        nullptr, nullptr, 0, 0);
    // 8) out[co][n] = BN(Ww[co][ci] . y[n][ci]) + v[co][n]
    hgemm<128, false, 4><<<dim3(NPIX / 128, CC / 128, BB), 256, SMN>>>(
        Wwhi, nullptr, y, nullptr, out, nullptr, nullptr,
        0, (size_t)NPIX * CHI, (size_t)CC * NPIX, NPIX,
        nullptr, v, (size_t)CC * NPIX, NPIX);
}

// round 5
// speedup vs baseline: 2.8143x; 1.2198x over previous
#include <cuda_runtime.h>
#include <cuda_fp16.h>
#include <cstdint>
#include <cstddef>

// Problem dims
#define BB   8
#define CC   256
#define CHI  128
#define HH   64
#define WW   64
#define NPIX 4096   // H*W
#define MPOOL 1024  // (H/2)*(W/2)

// ---------------- device scratch (no allocations allowed) ----------------
__device__ __half h_kT_hi[(size_t)BB * NPIX * CC];
__device__ __half h_kT_lo[(size_t)BB * NPIX * CC];
__device__ __half h_pq_hi[BB * MPOOL * CC];
__device__ __half h_pq_lo[BB * MPOOL * CC];
__device__ __half h_pv_hi[BB * MPOOL * CC];
__device__ __half h_Wth_hi[CHI * CC];
__device__ __half h_Wth_lo[CHI * CC];
__device__ __half h_Wph_hi[CHI * CC];
__device__ __half h_Wph_lo[CHI * CC];
__device__ __half h_Wg_hi[CHI * CC];
__device__ __half h_Ww_hi[CC * CHI];
__device__ __half h_th_hi[(size_t)BB * NPIX * CHI];
__device__ __half h_th_lo[(size_t)BB * NPIX * CHI];
__device__ __half h_ph_hi[BB * MPOOL * CHI];
__device__ __half h_ph_lo[BB * MPOOL * CHI];
__device__ __half h_g[BB * CHI * MPOOL];
__device__ __half h_y[(size_t)BB * NPIX * CHI];
__device__ float  g_bns[CC];
__device__ float  g_bnt[CC];

// ---------------- PTX helpers (all base-target, sm_80-level) ----------------
__device__ __forceinline__ uint32_t smem_u32(const void* p) {
    uint32_t a;
    asm("{ .reg .u64 t; cvta.to.shared.u64 t, %1; cvt.u32.u64 %0, t; }" : "=r"(a) : "l"(p));
    return a;
}
__device__ __forceinline__ void cp16(uint32_t d, const void* s) {
    asm volatile("cp.async.cg.shared.global [%0], [%1], 16;" :: "r"(d), "l"(s) : "memory");
}
__device__ __forceinline__ void cp_commit() {
    asm volatile("cp.async.commit_group;" ::: "memory");
}
template <int N>
__device__ __forceinline__ void cp_wait() {
    asm volatile("cp.async.wait_group %0;" :: "n"(N) : "memory");
}
__device__ __forceinline__ void ldsm4(uint32_t& r0, uint32_t& r1, uint32_t& r2, uint32_t& r3,
                                      uint32_t a) {
    asm volatile("ldmatrix.sync.aligned.m8n8.x4.shared.b16 {%0,%1,%2,%3}, [%4];"
                 : "=r"(r0), "=r"(r1), "=r"(r2), "=r"(r3) : "r"(a));
}
__device__ __forceinline__ void mma16816(float* c, const uint32_t* a, const uint32_t* b) {
    asm volatile(
        "mma.sync.aligned.m16n8k16.row.col.f32.f16.f16.f32 "
        "{%0,%1,%2,%3}, {%4,%5,%6,%7}, {%8,%9}, {%0,%1,%2,%3};"
        : "+f"(c[0]), "+f"(c[1]), "+f"(c[2]), "+f"(c[3])
        : "r"(a[0]), "r"(a[1]), "r"(a[2]), "r"(a[3]), "r"(b[0]), "r"(b[1]));
}
__device__ __forceinline__ uint32_t pkh2(float a, float b) {
    __half2 h = __floats2half2_rn(a, b);
    return *(uint32_t*)&h;
}

// ---------------- unified fp16 tensor-core GEMM (projections + final) ----------------
template <int K_TOTAL, bool SPLIT, int EPI>
__global__ void __launch_bounds__(256, 1) hgemm(
    const __half* __restrict__ Ahi, const __half* __restrict__ Alo,
    const __half* __restrict__ Bhi, const __half* __restrict__ Blo,
    float* __restrict__ Cf, __half* __restrict__ Ch, __half* __restrict__ Cl,
    size_t aB, size_t bB, size_t cB, int ldc,
    const float* __restrict__ bias,
    const float* __restrict__ resid, size_t rB, int ldr) {
    constexpr int NCH = K_TOTAL / 32;
    constexpr int STAGE = SPLIT ? 40960 : 20480;
    extern __shared__ char sm[];
    uint32_t sbase = smem_u32(sm);

    int tid = threadIdx.x, lane = tid & 31, w = tid >> 5;
    int wm = w >> 2, wn = w & 3;
    int z = blockIdx.z;

    const __half* Ag = Ahi + aB * z + (size_t)blockIdx.y * 128 * K_TOTAL;
    const __half* Bg = Bhi + bB * z + (size_t)blockIdx.x * 128 * K_TOTAL;
    const __half* Agl = SPLIT ? (Alo + aB * z + (size_t)blockIdx.y * 128 * K_TOTAL) : nullptr;
    const __half* Bgl = SPLIT ? (Blo + bB * z + (size_t)blockIdx.x * 128 * K_TOTAL) : nullptr;

    auto load_chunk = [&](int ch) {
        uint32_t st = sbase + (uint32_t)(ch & 1) * STAGE;
        int k0 = ch * 32;
#pragma unroll
        for (int t = 0; t < 2; t++) {
            int c = tid + t * 256;
            int row = c >> 2, j = c & 3;
            uint32_t d = st + row * 80 + j * 16;
            size_t go = (size_t)row * K_TOTAL + k0 + j * 8;
            cp16(d, Ag + go);
            cp16(d + 10240, Bg + go);
            if (SPLIT) {
                cp16(d + 20480, Agl + go);
                cp16(d + 30720, Bgl + go);
            }
        }
        cp_commit();
    };

    float acc[4][4][4];
#pragma unroll
    for (int i = 0; i < 4; i++)
#pragma unroll
        for (int j = 0; j < 4; j++)
#pragma unroll
            for (int e = 0; e < 4; e++) acc[i][j][e] = 0.f;

    load_chunk(0);

    for (int ch = 0; ch < NCH; ch++) {
        if (ch + 1 < NCH) {
            load_chunk(ch + 1);
            cp_wait<1>();
        } else {
            cp_wait<0>();
        }
        __syncthreads();
        uint32_t sa = sbase + (uint32_t)(ch & 1) * STAGE;
        uint32_t sb = sa + 10240;
#pragma unroll
        for (int k16 = 0; k16 < 2; k16++) {
            uint32_t a[4][4], b[4][2];
            uint32_t coff = (uint32_t)(k16 * 32 + (lane >> 4) * 16);
#pragma unroll
            for (int mi = 0; mi < 4; mi++) {
                uint32_t ad = sa + (uint32_t)(wm * 64 + mi * 16 + (lane & 15)) * 80 + coff;
                ldsm4(a[mi][0], a[mi][1], a[mi][2], a[mi][3], ad);
            }
#pragma unroll
            for (int nh = 0; nh < 2; nh++) {
                uint32_t bd = sb + (uint32_t)(wn * 32 + nh * 16 + (lane & 15)) * 80 + coff;
                uint32_t r0, r1, r2, r3;
                ldsm4(r0, r1, r2, r3, bd);
                b[nh * 2 + 0][0] = r0; b[nh * 2 + 0][1] = r2;
                b[nh * 2 + 1][0] = r1; b[nh * 2 + 1][1] = r3;
            }
#pragma unroll
            for (int mi = 0; mi < 4; mi++)
#pragma unroll
                for (int ni = 0; ni < 4; ni++) mma16816(acc[mi][ni], a[mi], b[ni]);
            if (SPLIT) {
                uint32_t al[4][4], bl[4][2];
#pragma unroll
                for (int mi = 0; mi < 4; mi++) {
                    uint32_t ad = sa + 20480 + (uint32_t)(wm * 64 + mi * 16 + (lane & 15)) * 80 + coff;
                    ldsm4(al[mi][0], al[mi][1], al[mi][2], al[mi][3], ad);
                }
#pragma unroll
                for (int nh = 0; nh < 2; nh++) {
                    uint32_t bd = sa + 30720 + (uint32_t)(wn * 32 + nh * 16 + (lane & 15)) * 80 + coff;
                    uint32_t r0, r1, r2, r3;
                    ldsm4(r0, r1, r2, r3, bd);
                    bl[nh * 2 + 0][0] = r0; bl[nh * 2 + 0][1] = r2;
                    bl[nh * 2 + 1][0] = r1; bl[nh * 2 + 1][1] = r3;
                }
#pragma unroll
                for (int mi = 0; mi < 4; mi++)
#pragma unroll
                    for (int ni = 0; ni < 4; ni++) {
                        mma16816(acc[mi][ni], a[mi], bl[ni]);
                        mma16816(acc[mi][ni], al[mi], b[ni]);
                    }
            }
        }
        __syncthreads();
    }

    int r = lane >> 2, cp2 = (lane & 3) * 2;
    int row0 = blockIdx.y * 128 + wm * 64;
    int col0 = blockIdx.x * 128 + wn * 32;
    float* Cfz = (EPI == 0 || EPI == 4) ? Cf + cB * z : nullptr;
    __half* Chz = (EPI == 1 || EPI == 2 || EPI == 3) ? Ch + cB * z : nullptr;
    __half* Clz = (EPI == 1) ? Cl + cB * z : nullptr;
    const float* Rz = (EPI == 4) ? resid + rB * z : nullptr;

#pragma unroll
    for (int mi = 0; mi < 4; mi++) {
#pragma unroll
        for (int h = 0; h < 2; h++) {
            int row = row0 + mi * 16 + h * 8 + r;
            float s = 1.f, t = 0.f;
            if (EPI == 2) t = bias[row];
            if (EPI == 4) { s = g_bns[row]; t = g_bnt[row]; }
#pragma unroll
            for (int ni = 0; ni < 4; ni++) {
                int col = col0 + ni * 8 + cp2;
                float v0 = acc[mi][ni][h * 2 + 0];
                float v1 = acc[mi][ni][h * 2 + 1];
                if (EPI == 0) {
                    *(float2*)(Cfz + (size_t)row * ldc + col) = make_float2(v0, v1);
                } else if (EPI == 1) {
                    v0 += bias[col]; v1 += bias[col + 1];
                    __half h0 = __float2half_rn(v0), h1 = __float2half_rn(v1);
                    *(__half2*)(Chz + (size_t)row * ldc + col) = __halves2half2(h0, h1);
                    __half l0 = __float2half_rn(v0 - __half2float(h0));
                    __half l1 = __float2half_rn(v1 - __half2float(h1));
                    *(__half2*)(Clz + (size_t)row * ldc + col) = __halves2half2(l0, l1);
                } else if (EPI == 2 || EPI == 3) {
                    float u0 = v0 + t, u1 = v1 + t;
                    *(__half2*)(Chz + (size_t)row * ldc + col) =
                        __halves2half2(__float2half_rn(u0), __float2half_rn(u1));
                } else {
                    float2 rr = *(const float2*)(Rz + (size_t)row * ldr + col);
                    *(float2*)(Cfz + (size_t)row * ldc + col) =
                        make_float2(v0 * s + t + rr.x, v1 * s + t + rr.y);
                }
            }
        }
    }
}

// ---------------- fused flash attention: S = theta.phi^T (split), softmax, y = P.g ----------------
// Block: 128 q-rows (blockIdx.x tile), batch blockIdx.y. 8 warps x 16 rows.
// Loop over 16 m-tiles of 64. smem: theta (hi+lo) resident + 2-stage (phi hi/lo + g).
__global__ void __launch_bounds__(256, 1) flash_kernel(
    const __half* __restrict__ Thi, const __half* __restrict__ Tlo,
    const __half* __restrict__ Phh, const __half* __restrict__ Phl,
    const __half* __restrict__ G, __half* __restrict__ Y) {
    extern __shared__ char sm[];
    uint32_t sbase = smem_u32(sm);
    const uint32_t STG = 81920, STGSZ = 61440;  // stage: phi_hi 0, phi_lo +20480, g +40960

    int tid = threadIdx.x, lane = tid & 31, w = tid >> 5;
    int b = blockIdx.y;
    int n0 = blockIdx.x * 128;
    const __half* tb_hi = Thi + ((size_t)b * NPIX + n0) * CHI;
    const __half* tb_lo = Tlo + ((size_t)b * NPIX + n0) * CHI;
    const __half* pb_hi = Phh + (size_t)b * MPOOL * CHI;
    const __half* pb_lo = Phl + (size_t)b * MPOOL * CHI;
    const __half* gb = G + (size_t)b * CHI * MPOOL;

    // resident theta tile: 128 rows x 128 ci (hi at 0, lo at +40960), 4 k-chunks of 32
#pragma unroll
    for (int t = 0; t < 8; t++) {
        int idx = tid + t * 256;
        int row = idx >> 4, j = idx & 15;
        uint32_t d = sbase + (uint32_t)(j >> 2) * 10240 + row * 80 + (j & 3) * 16;
        size_t go = (size_t)row * CHI + j * 8;
        cp16(d, tb_hi + go);
        cp16(d + 40960, tb_lo + go);
    }

    auto load_stage = [&](int mt) {
        uint32_t st = sbase + STG + (uint32_t)(mt & 1) * STGSZ;
        int m0 = mt * 64;
#pragma unroll
        for (int t = 0; t < 4; t++) {
            int idx = tid + t * 256;
            int row = idx >> 4, j = idx & 15;
            uint32_t d = st + (uint32_t)(j >> 2) * 5120 + row * 80 + (j & 3) * 16;
            size_t go = (size_t)(m0 + row) * CHI + j * 8;
            cp16(d, pb_hi + go);
            cp16(d + 20480, pb_lo + go);
        }
#pragma unroll
        for (int t = 0; t < 4; t++) {
            int idx = tid + t * 256;
            int row = idx >> 3, j = idx & 7;
            uint32_t d = st + 40960 + (uint32_t)(j >> 2) * 10240 + row * 80 + (j & 3) * 16;
            cp16(d, gb + (size_t)row * MPOOL + m0 + j * 8);
        }
        cp_commit();
    };
    load_stage(0);

    float yacc[16][4];
#pragma unroll
    for (int j = 0; j < 16; j++)
#pragma unroll
        for (int e = 0; e < 4; e++) yacc[j][e] = 0.f;
    float rmax0 = -1e30f, rmax1 = -1e30f, rsum0 = 0.f, rsum1 = 0.f;

    for (int mt = 0; mt < 16; mt++) {
        if (mt + 1 < 16) {
            load_stage(mt + 1);
            cp_wait<1>();
        } else {
            cp_wait<0>();
        }
        __syncthreads();
        uint32_t st = sbase + STG + (uint32_t)(mt & 1) * STGSZ;

        // ---- S = theta . phi^T (3-pass split), 16 rows x 64 m per warp ----
        float sacc[8][4];
#pragma unroll
        for (int j = 0; j < 8; j++)
#pragma unroll
            for (int e = 0; e < 4; e++) sacc[j][e] = 0.f;

#pragma unroll
        for (int s = 0; s < 8; s++) {
            uint32_t chunk = (uint32_t)(s >> 1);
            uint32_t inner = (uint32_t)((s & 1) * 32 + (lane >> 4) * 16);
            uint32_t arow = (uint32_t)(w * 16 + (lane & 15)) * 80;
            uint32_t ah[4], al[4];
            ldsm4(ah[0], ah[1], ah[2], ah[3], sbase + chunk * 10240 + arow + inner);
            ldsm4(al[0], al[1], al[2], al[3], sbase + 40960 + chunk * 10240 + arow + inner);
            uint32_t bh[8][2], bl[8][2];
#pragma unroll
            for (int p = 0; p < 4; p++) {
                uint32_t brow = (uint32_t)(p * 16 + (lane & 15)) * 80;
                uint32_t bad = st + chunk * 5120 + brow + inner;
                uint32_t r0, r1, r2, r3;
                ldsm4(r0, r1, r2, r3, bad);
                bh[2 * p][0] = r0; bh[2 * p][1] = r2;
                bh[2 * p + 1][0] = r1; bh[2 * p + 1][1] = r3;
                ldsm4(r0, r1, r2, r3, bad + 20480);
                bl[2 * p][0] = r0; bl[2 * p][1] = r2;
                bl[2 * p + 1][0] = r1; bl[2 * p + 1][1] = r3;
            }
#pragma unroll
            for (int j = 0; j < 8; j++) {
                mma16816(sacc[j], ah, bh[j]);
                mma16816(sacc[j], ah, bl[j]);
                mma16816(sacc[j], al, bh[j]);
            }
        }

        // ---- online softmax update (rows r and r+8 per thread) ----
        float tm0 = -1e30f, tm1 = -1e30f;
#pragma unroll
        for (int j = 0; j < 8; j++) {
            tm0 = fmaxf(tm0, fmaxf(sacc[j][0], sacc[j][1]));
            tm1 = fmaxf(tm1, fmaxf(sacc[j][2], sacc[j][3]));
        }
        tm0 = fmaxf(tm0, __shfl_xor_sync(0xffffffffu, tm0, 1));
        tm0 = fmaxf(tm0, __shfl_xor_sync(0xffffffffu, tm0, 2));
        tm1 = fmaxf(tm1, __shfl_xor_sync(0xffffffffu, tm1, 1));
        tm1 = fmaxf(tm1, __shfl_xor_sync(0xffffffffu, tm1, 2));
        float mn0 = fmaxf(rmax0, tm0), mn1 = fmaxf(rmax1, tm1);
        float sc0 = __expf(rmax0 - mn0), sc1 = __expf(rmax1 - mn1);
        float ts0 = 0.f, ts1 = 0.f;
#pragma unroll
        for (int j = 0; j < 8; j++) {
            sacc[j][0] = __expf(sacc[j][0] - mn0);
            sacc[j][1] = __expf(sacc[j][1] - mn0);
            sacc[j][2] = __expf(sacc[j][2] - mn1);
            sacc[j][3] = __expf(sacc[j][3] - mn1);
            ts0 += sacc[j][0] + sacc[j][1];
            ts1 += sacc[j][2] + sacc[j][3];
        }
        ts0 += __shfl_xor_sync(0xffffffffu, ts0, 1);
        ts0 += __shfl_xor_sync(0xffffffffu, ts0, 2);
        ts1 += __shfl_xor_sync(0xffffffffu, ts1, 1);
        ts1 += __shfl_xor_sync(0xffffffffu, ts1, 2);
        rsum0 = rsum0 * sc0 + ts0;
        rsum1 = rsum1 * sc1 + ts1;
        rmax0 = mn0; rmax1 = mn1;
#pragma unroll
        for (int j = 0; j < 16; j++) {
            yacc[j][0] *= sc0; yacc[j][1] *= sc0;
            yacc[j][2] *= sc1; yacc[j][3] *= sc1;
        }

        // ---- pack P into A-frags (k = m dimension) ----
        uint32_t pf[4][4];
#pragma unroll
        for (int s2 = 0; s2 < 4; s2++) {
            pf[s2][0] = pkh2(sacc[2 * s2][0], sacc[2 * s2][1]);
            pf[s2][1] = pkh2(sacc[2 * s2][2], sacc[2 * s2][3]);
            pf[s2][2] = pkh2(sacc[2 * s2 + 1][0], sacc[2 * s2 + 1][1]);
            pf[s2][3] = pkh2(sacc[2 * s2 + 1][2], sacc[2 * s2 + 1][3]);
        }

        // ---- y += P . g  (B = g[ci][m] K-major, n = ci) ----
#pragma unroll
        for (int s2 = 0; s2 < 4; s2++) {
            uint32_t chunk = (uint32_t)(s2 >> 1);
            uint32_t inner = (uint32_t)((s2 & 1) * 32 + (lane >> 4) * 16);
#pragma unroll
            for (int pc = 0; pc < 8; pc++) {
                uint32_t brow = (uint32_t)(pc * 16 + (lane & 15)) * 80;
                uint32_t r0, r1, r2, r3;
                ldsm4(r0, r1, r2, r3, st + 40960 + chunk * 10240 + brow + inner);
                uint32_t bb0[2] = {r0, r2};
                uint32_t bb1[2] = {r1, r3};
                mma16816(yacc[2 * pc], pf[s2], bb0);
                mma16816(yacc[2 * pc + 1], pf[s2], bb1);
            }
        }
        __syncthreads();
    }

    // ---- normalize + write y fp16 [n][ci] ----
    float inv0 = 1.f / rsum0, inv1 = 1.f / rsum1;
    int r = lane >> 2, c2 = (lane & 3) * 2;
    size_t rowbase = (size_t)b * NPIX + n0 + w * 16;
#pragma unroll
    for (int j = 0; j < 16; j++) {
        int col = j * 8 + c2;
        uint32_t v0 = pkh2(yacc[j][0] * inv0, yacc[j][1] * inv0);
        uint32_t v1 = pkh2(yacc[j][2] * inv1, yacc[j][3] * inv1);
        *(uint32_t*)(Y + (rowbase + r) * CHI + col) = v0;
        *(uint32_t*)(Y + (rowbase + r + 8) * CHI + col) = v1;
    }
}

// ---------------- weight prep: fp32 -> fp16 hi/lo + BN constants ----------------
__global__ void wprep_kernel(const float* __restrict__ Wth, const float* __restrict__ Wph,
                             const float* __restrict__ Wg, const float* __restrict__ Ww,
                             const float* __restrict__ gamma, const float* __restrict__ beta,
                             const float* __restrict__ mean, const float* __restrict__ var,
                             const float* __restrict__ bw) {
    int i = blockIdx.x * 256 + threadIdx.x;
    float a = Wth[i];
    __half h = __float2half_rn(a);
    h_Wth_hi[i] = h;
    h_Wth_lo[i] = __float2half_rn(a - __half2float(h));
    float b = Wph[i];
    __half hb = __float2half_rn(b);
    h_Wph_hi[i] = hb;
    h_Wph_lo[i] = __float2half_rn(b - __half2float(hb));
    h_Wg_hi[i] = __float2half_rn(Wg[i]);
    h_Ww_hi[i] = __float2half_rn(Ww[i]);
    if (i < CC) {
        float sc = gamma[i] * rsqrtf(var[i] + 1e-5f);
        g_bns[i] = sc;
        g_bnt[i] = beta[i] + (bw[i] - mean[i]) * sc;
    }
}

// ---------------- pool(2x2) + transpose -> fp16 [m][c] ----------------
__global__ void __launch_bounds__(256) pooltrans_kernel(const float* __restrict__ q,
                                                        const float* __restrict__ v) {
    __shared__ float ts[32][33];
    int z = blockIdx.z;
    bool isq = (z < BB);
    const float* src = isq ? q : v;
    int b = z & (BB - 1);
    int m0 = blockIdx.x * 32, c0 = blockIdx.y * 32;
    int tx = threadIdx.x, ty = threadIdx.y;
    const float* sb = src + (size_t)b * CC * NPIX;
    int m = m0 + tx, mi = m >> 5, mj = m & 31;
#pragma unroll
    for (int i = 0; i < 4; i++) {
        int c = c0 + ty + i * 8;
        const float* p = sb + (size_t)c * NPIX + (2 * mi) * WW + 2 * mj;
        ts[ty + i * 8][tx] = 0.25f * (p[0] + p[1] + p[WW] + p[WW + 1]);
    }
    __syncthreads();
    size_t base = (size_t)b * MPOOL * CC;
#pragma unroll
    for (int i = 0; i < 4; i++) {
        float val = ts[tx][ty + i * 8];
        size_t idx = base + (size_t)(m0 + ty + i * 8) * CC + c0 + tx;
        __half h = __float2half_rn(val);
        if (isq) {
            h_pq_hi[idx] = h;
            h_pq_lo[idx] = __float2half_rn(val - __half2float(h));
        } else {
            h_pv_hi[idx] = h;
        }
    }
}

// ---------------- transpose k: [c][n] -> fp16 hi/lo [n][c] ----------------
__global__ void __launch_bounds__(256) transk_kernel(const float* __restrict__ k) {
    __shared__ float ts[32][33];
    int b = blockIdx.z;
    int n0 = blockIdx.x * 32, c0 = blockIdx.y * 32;
    int tx = threadIdx.x, ty = threadIdx.y;
    const float* sb = k + (size_t)b * CC * NPIX;
#pragma unroll
    for (int i = 0; i < 4; i++)
        ts[ty + i * 8][tx] = sb[(size_t)(c0 + ty + i * 8) * NPIX + n0 + tx];
    __syncthreads();
    size_t base = (size_t)b * NPIX * CC;
#pragma unroll
    for (int i = 0; i < 4; i++) {
        float val = ts[tx][ty + i * 8];
        size_t idx = base + (size_t)(n0 + ty + i * 8) * CC + c0 + tx;
        __half h = __float2half_rn(val);
        h_kT_hi[idx] = h;
        h_kT_lo[idx] = __float2half_rn(val - __half2float(h));
    }
}

// ---------------- launch ----------------
extern "C" void kernel_launch(void* const* d_in, const int* in_sizes, int n_in,
                              void* d_out, int out_size) {
    (void)in_sizes; (void)n_in; (void)out_size;
    const float* q     = (const float*)d_in[0];
    const float* k     = (const float*)d_in[1];
    const float* v     = (const float*)d_in[2];
    const float* Wg    = (const float*)d_in[3];
    const float* bg    = (const float*)d_in[4];
    const float* Wth   = (const float*)d_in[5];
    const float* bth   = (const float*)d_in[6];
    const float* Wph   = (const float*)d_in[7];
    const float* bph   = (const float*)d_in[8];
    const float* Ww    = (const float*)d_in[9];
    const float* bw    = (const float*)d_in[10];
    const float* gamma = (const float*)d_in[11];
    const float* beta  = (const float*)d_in[12];
    const float* mean  = (const float*)d_in[13];
    const float* var   = (const float*)d_in[14];
    float* out = (float*)d_out;

    __half *kThi, *kTlo, *pqhi, *pqlo, *pvhi;
    __half *Wthhi, *Wthlo, *Wphhi, *Wphlo, *Wghi, *Wwhi;
    __half *thhi, *thlo, *phhi, *phlo, *gmat, *y;
    cudaGetSymbolAddress((void**)&kThi, h_kT_hi);
    cudaGetSymbolAddress((void**)&kTlo, h_kT_lo);
    cudaGetSymbolAddress((void**)&pqhi, h_pq_hi);
    cudaGetSymbolAddress((void**)&pqlo, h_pq_lo);
    cudaGetSymbolAddress((void**)&pvhi, h_pv_hi);
    cudaGetSymbolAddress((void**)&Wthhi, h_Wth_hi);
    cudaGetSymbolAddress((void**)&Wthlo, h_Wth_lo);
    cudaGetSymbolAddress((void**)&Wphhi, h_Wph_hi);
    cudaGetSymbolAddress((void**)&Wphlo, h_Wph_lo);
    cudaGetSymbolAddress((void**)&Wghi, h_Wg_hi);
    cudaGetSymbolAddress((void**)&Wwhi, h_Ww_hi);
    cudaGetSymbolAddress((void**)&thhi, h_th_hi);
    cudaGetSymbolAddress((void**)&thlo, h_th_lo);
    cudaGetSymbolAddress((void**)&phhi, h_ph_hi);
    cudaGetSymbolAddress((void**)&phlo, h_ph_lo);
    cudaGetSymbolAddress((void**)&gmat, h_g);
    cudaGetSymbolAddress((void**)&y, h_y);

    const int SMS = 81920;   // split hgemm: 2 stages x 40KB
    const int SMN = 40960;   // plain hgemm: 2 stages x 20KB
    const int SMF = 204800;  // flash: theta 80KB + 2 stages x 60KB
    cudaFuncSetAttribute(hgemm<256, true, 1>, cudaFuncAttributeMaxDynamicSharedMemorySize, SMS);
    cudaFuncSetAttribute(hgemm<256, false, 2>, cudaFuncAttributeMaxDynamicSharedMemorySize, SMN);
    cudaFuncSetAttribute(hgemm<128, false, 4>, cudaFuncAttributeMaxDynamicSharedMemorySize, SMN);
    cudaFuncSetAttribute(flash_kernel, cudaFuncAttributeMaxDynamicSharedMemorySize, SMF);

    // 1) prep
    wprep_kernel<<<CHI * CC / 256, 256>>>(Wth, Wph, Wg, Ww, gamma, beta, mean, var, bw);
    pooltrans_kernel<<<dim3(MPOOL / 32, CC / 32, 2 * BB), dim3(32, 8)>>>(q, v);
    transk_kernel<<<dim3(NPIX / 32, CC / 32, BB), dim3(32, 8)>>>(k);

    // 2) theta[n][ci] = kT[n][c] . Wth[ci][c]  (split, +bth, split-write)
    hgemm<256, true, 1><<<dim3(1, NPIX / 128, BB), 256, SMS>>>(
        kThi, kTlo, Wthhi, Wthlo, nullptr, thhi, thlo,
        (size_t)NPIX * CC, 0, (size_t)NPIX * CHI, CHI, bth, nullptr, 0, 0);
    // 3) phi[m][ci] = pq[m][c] . Wph[ci][c]
    hgemm<256, true, 1><<<dim3(1, MPOOL / 128, BB), 256, SMS>>>(
        pqhi, pqlo, Wphhi, Wphlo, nullptr, phhi, phlo,
        (size_t)MPOOL * CC, 0, (size_t)MPOOL * CHI, CHI, bph, nullptr, 0, 0);
    // 4) g[ci][m] = Wg[ci][c] . pv[m][c]  (+bg[row], fp16)
    hgemm<256, false, 2><<<dim3(MPOOL / 128, 1, BB), 256, SMN>>>(
        Wghi, nullptr, pvhi, nullptr, nullptr, gmat, nullptr,
        0, (size_t)MPOOL * CC, (size_t)CHI * MPOOL, MPOOL, bg, nullptr, 0, 0);
    // 5) fused: S -> softmax -> y
    flash_kernel<<<dim3(NPIX / 128, BB), 256, SMF>>>(thhi, thlo, phhi, phlo, gmat, y);
    // 6) out[co][n] = BN(Ww[co][ci] . y[n][ci]) + v[co][n]
    hgemm<128, false, 4><<<dim3(NPIX / 128, CC / 128, BB), 256, SMN>>>(
        Wwhi, nullptr, y, nullptr, out, nullptr, nullptr,
        0, (size_t)NPIX * CHI, (size_t)CC * NPIX, NPIX,
        nullptr, v, (size_t)CC * NPIX, NPIX);
}

// round 6
// speedup vs baseline: 2.8866x; 1.0257x over previous
#include <cuda_runtime.h>
#include <cuda_fp16.h>
#include <cstdint>
#include <cstddef>

// Problem dims
#define BB   8
#define CC   256
#define CHI  128
#define HH   64
#define WW   64
#define NPIX 4096   // H*W
#define MPOOL 1024  // (H/2)*(W/2)

// ---------------- device scratch (no allocations allowed) ----------------
__device__ __half h_kT_hi[(size_t)BB * NPIX * CC];
__device__ __half h_kT_lo[(size_t)BB * NPIX * CC];
__device__ __half h_pq_hi[BB * MPOOL * CC];
__device__ __half h_pq_lo[BB * MPOOL * CC];
__device__ __half h_pv_hi[BB * MPOOL * CC];
__device__ __half h_Wth_hi[CHI * CC];
__device__ __half h_Wth_lo[CHI * CC];
__device__ __half h_Wph_hi[CHI * CC];
__device__ __half h_Wph_lo[CHI * CC];
__device__ __half h_Wg_hi[CHI * CC];
__device__ __half h_Ww_hi[CC * CHI];
__device__ __half h_ph_hi[BB * MPOOL * CHI];
__device__ __half h_ph_lo[BB * MPOOL * CHI];
__device__ __half h_g[BB * CHI * MPOOL];
__device__ __half h_y[(size_t)BB * NPIX * CHI];
__device__ float  g_bns[CC];
__device__ float  g_bnt[CC];

// ---------------- PTX helpers (all base-target, sm_80-level) ----------------
__device__ __forceinline__ uint32_t smem_u32(const void* p) {
    uint32_t a;
    asm("{ .reg .u64 t; cvta.to.shared.u64 t, %1; cvt.u32.u64 %0, t; }" : "=r"(a) : "l"(p));
    return a;
}
__device__ __forceinline__ void cp16(uint32_t d, const void* s) {
    asm volatile("cp.async.cg.shared.global [%0], [%1], 16;" :: "r"(d), "l"(s) : "memory");
}
__device__ __forceinline__ void cp_commit() {
    asm volatile("cp.async.commit_group;" ::: "memory");
}
template <int N>
__device__ __forceinline__ void cp_wait() {
    asm volatile("cp.async.wait_group %0;" :: "n"(N) : "memory");
}
__device__ __forceinline__ void ldsm4(uint32_t& r0, uint32_t& r1, uint32_t& r2, uint32_t& r3,
                                      uint32_t a) {
    asm volatile("ldmatrix.sync.aligned.m8n8.x4.shared.b16 {%0,%1,%2,%3}, [%4];"
                 : "=r"(r0), "=r"(r1), "=r"(r2), "=r"(r3) : "r"(a));
}
__device__ __forceinline__ void mma16816(float* c, const uint32_t* a, const uint32_t* b) {
    asm volatile(
        "mma.sync.aligned.m16n8k16.row.col.f32.f16.f16.f32 "
        "{%0,%1,%2,%3}, {%4,%5,%6,%7}, {%8,%9}, {%0,%1,%2,%3};"
        : "+f"(c[0]), "+f"(c[1]), "+f"(c[2]), "+f"(c[3])
        : "r"(a[0]), "r"(a[1]), "r"(a[2]), "r"(a[3]), "r"(b[0]), "r"(b[1]));
}
__device__ __forceinline__ uint32_t pkh2(float a, float b) {
    __half2 h = __floats2half2_rn(a, b);
    return *(uint32_t*)&h;
}

// ---------------- unified fp16 tensor-core GEMM (projections + final) ----------------
template <int K_TOTAL, bool SPLIT, int EPI>
__global__ void __launch_bounds__(256, 1) hgemm(
    const __half* __restrict__ Ahi, const __half* __restrict__ Alo,
    const __half* __restrict__ Bhi, const __half* __restrict__ Blo,
    float* __restrict__ Cf, __half* __restrict__ Ch, __half* __restrict__ Cl,
    size_t aB, size_t bB, size_t cB, int ldc,
    const float* __restrict__ bias,
    const float* __restrict__ resid, size_t rB, int ldr) {
    constexpr int NCH = K_TOTAL / 32;
    constexpr int STAGE = SPLIT ? 40960 : 20480;
    extern __shared__ char sm[];
    uint32_t sbase = smem_u32(sm);

    int tid = threadIdx.x, lane = tid & 31, w = tid >> 5;
    int wm = w >> 2, wn = w & 3;
    int z = blockIdx.z;

    const __half* Ag = Ahi + aB * z + (size_t)blockIdx.y * 128 * K_TOTAL;
    const __half* Bg = Bhi + bB * z + (size_t)blockIdx.x * 128 * K_TOTAL;
    const __half* Agl = SPLIT ? (Alo + aB * z + (size_t)blockIdx.y * 128 * K_TOTAL) : nullptr;
    const __half* Bgl = SPLIT ? (Blo + bB * z + (size_t)blockIdx.x * 128 * K_TOTAL) : nullptr;

    auto load_chunk = [&](int ch) {
        uint32_t st = sbase + (uint32_t)(ch & 1) * STAGE;
        int k0 = ch * 32;
#pragma unroll
        for (int t = 0; t < 2; t++) {
            int c = tid + t * 256;
            int row = c >> 2, j = c & 3;
            uint32_t d = st + row * 80 + j * 16;
            size_t go = (size_t)row * K_TOTAL + k0 + j * 8;
            cp16(d, Ag + go);
            cp16(d + 10240, Bg + go);
            if (SPLIT) {
                cp16(d + 20480, Agl + go);
                cp16(d + 30720, Bgl + go);
            }
        }
        cp_commit();
    };

    float acc[4][4][4];
#pragma unroll
    for (int i = 0; i < 4; i++)
#pragma unroll
        for (int j = 0; j < 4; j++)
#pragma unroll
            for (int e = 0; e < 4; e++) acc[i][j][e] = 0.f;

    load_chunk(0);

    for (int ch = 0; ch < NCH; ch++) {
        if (ch + 1 < NCH) {
            load_chunk(ch + 1);
            cp_wait<1>();
        } else {
            cp_wait<0>();
        }
        __syncthreads();
        uint32_t sa = sbase + (uint32_t)(ch & 1) * STAGE;
        uint32_t sb = sa + 10240;
#pragma unroll
        for (int k16 = 0; k16 < 2; k16++) {
            uint32_t a[4][4], b[4][2];
            uint32_t coff = (uint32_t)(k16 * 32 + (lane >> 4) * 16);
#pragma unroll
            for (int mi = 0; mi < 4; mi++) {
                uint32_t ad = sa + (uint32_t)(wm * 64 + mi * 16 + (lane & 15)) * 80 + coff;
                ldsm4(a[mi][0], a[mi][1], a[mi][2], a[mi][3], ad);
            }
#pragma unroll
            for (int nh = 0; nh < 2; nh++) {
                uint32_t bd = sb + (uint32_t)(wn * 32 + nh * 16 + (lane & 15)) * 80 + coff;
                uint32_t r0, r1, r2, r3;
                ldsm4(r0, r1, r2, r3, bd);
                b[nh * 2 + 0][0] = r0; b[nh * 2 + 0][1] = r2;
                b[nh * 2 + 1][0] = r1; b[nh * 2 + 1][1] = r3;
            }
#pragma unroll
            for (int mi = 0; mi < 4; mi++)
#pragma unroll
                for (int ni = 0; ni < 4; ni++) mma16816(acc[mi][ni], a[mi], b[ni]);
            if (SPLIT) {
                uint32_t al[4][4], bl[4][2];
#pragma unroll
                for (int mi = 0; mi < 4; mi++) {
                    uint32_t ad = sa + 20480 + (uint32_t)(wm * 64 + mi * 16 + (lane & 15)) * 80 + coff;
                    ldsm4(al[mi][0], al[mi][1], al[mi][2], al[mi][3], ad);
                }
#pragma unroll
                for (int nh = 0; nh < 2; nh++) {
                    uint32_t bd = sa + 30720 + (uint32_t)(wn * 32 + nh * 16 + (lane & 15)) * 80 + coff;
                    uint32_t r0, r1, r2, r3;
                    ldsm4(r0, r1, r2, r3, bd);
                    bl[nh * 2 + 0][0] = r0; bl[nh * 2 + 0][1] = r2;
                    bl[nh * 2 + 1][0] = r1; bl[nh * 2 + 1][1] = r3;
                }
#pragma unroll
                for (int mi = 0; mi < 4; mi++)
#pragma unroll
                    for (int ni = 0; ni < 4; ni++) {
                        mma16816(acc[mi][ni], a[mi], bl[ni]);
                        mma16816(acc[mi][ni], al[mi], b[ni]);
                    }
            }
        }
        __syncthreads();
    }

    int r = lane >> 2, cp2 = (lane & 3) * 2;
    int row0 = blockIdx.y * 128 + wm * 64;
    int col0 = blockIdx.x * 128 + wn * 32;
    float* Cfz = (EPI == 0 || EPI == 4) ? Cf + cB * z : nullptr;
    __half* Chz = (EPI == 1 || EPI == 2 || EPI == 3) ? Ch + cB * z : nullptr;
    __half* Clz = (EPI == 1) ? Cl + cB * z : nullptr;
    const float* Rz = (EPI == 4) ? resid + rB * z : nullptr;

#pragma unroll
    for (int mi = 0; mi < 4; mi++) {
#pragma unroll
        for (int h = 0; h < 2; h++) {
            int row = row0 + mi * 16 + h * 8 + r;
            float s = 1.f, t = 0.f;
            if (EPI == 2) t = bias[row];
            if (EPI == 4) { s = g_bns[row]; t = g_bnt[row]; }
#pragma unroll
            for (int ni = 0; ni < 4; ni++) {
                int col = col0 + ni * 8 + cp2;
                float v0 = acc[mi][ni][h * 2 + 0];
                float v1 = acc[mi][ni][h * 2 + 1];
                if (EPI == 0) {
                    *(float2*)(Cfz + (size_t)row * ldc + col) = make_float2(v0, v1);
                } else if (EPI == 1) {
                    v0 += bias[col]; v1 += bias[col + 1];
                    __half h0 = __float2half_rn(v0), h1 = __float2half_rn(v1);
                    *(__half2*)(Chz + (size_t)row * ldc + col) = __halves2half2(h0, h1);
                    __half l0 = __float2half_rn(v0 - __half2float(h0));
                    __half l1 = __float2half_rn(v1 - __half2float(h1));
                    *(__half2*)(Clz + (size_t)row * ldc + col) = __halves2half2(l0, l1);
                } else if (EPI == 2 || EPI == 3) {
                    float u0 = v0 + t, u1 = v1 + t;
                    *(__half2*)(Chz + (size_t)row * ldc + col) =
                        __halves2half2(__float2half_rn(u0), __float2half_rn(u1));
                } else {
                    float2 rr = *(const float2*)(Rz + (size_t)row * ldr + col);
                    *(float2*)(Cfz + (size_t)row * ldc + col) =
                        make_float2(v0 * s + t + rr.x, v1 * s + t + rr.y);
                }
            }
        }
    }
}

// ---------------- fused flash: theta-projection prologue + S-softmax-y loop ----------------
// Block = 128 q-rows x batch. Prologue computes theta = kT.Wth^T + bth (3-pass split)
// and keeps theta as hi/lo fp16 A-fragments in registers. Main loop then streams
// phi (hi/lo) and g, with NO A-side ldsm.
__global__ void __launch_bounds__(256, 1) flash_kernel(
    const __half* __restrict__ KThi, const __half* __restrict__ KTlo,
    const __half* __restrict__ Wth_hi, const __half* __restrict__ Wth_lo,
    const float* __restrict__ bth,
    const __half* __restrict__ Phh, const __half* __restrict__ Phl,
    const __half* __restrict__ G, __half* __restrict__ Y) {
    extern __shared__ char sm[];
    uint32_t sbase = smem_u32(sm);
    const uint32_t STGSZ = 61440;

    int tid = threadIdx.x, lane = tid & 31, w = tid >> 5;
    int b = blockIdx.y;
    int n0 = blockIdx.x * 128;
    const __half* kb_hi = KThi + ((size_t)b * NPIX + n0) * CC;
    const __half* kb_lo = KTlo + ((size_t)b * NPIX + n0) * CC;
    const __half* pb_hi = Phh + (size_t)b * MPOOL * CHI;
    const __half* pb_lo = Phl + (size_t)b * MPOOL * CHI;
    const __half* gb = G + (size_t)b * CHI * MPOOL;

    // ======== PROLOGUE: theta tile via split GEMM (K=256, 8 chunks of 32) ========
    auto load_pchunk = [&](int ch) {
        uint32_t st = sbase + (uint32_t)(ch & 1) * STGSZ;
        int k0 = ch * 32;
#pragma unroll
        for (int t = 0; t < 2; t++) {
            int c = tid + t * 256;
            int row = c >> 2, j = c & 3;
            uint32_t d = st + row * 80 + j * 16;
            size_t go = (size_t)row * CC + k0 + j * 8;
            cp16(d, kb_hi + go);
            cp16(d + 10240, kb_lo + go);
            cp16(d + 20480, Wth_hi + go);
            cp16(d + 30720, Wth_lo + go);
        }
        cp_commit();
    };

    float acc[16][4];
#pragma unroll
    for (int j = 0; j < 16; j++)
#pragma unroll
        for (int e = 0; e < 4; e++) acc[j][e] = 0.f;

    load_pchunk(0);
    for (int ch = 0; ch < 8; ch++) {
        if (ch + 1 < 8) {
            load_pchunk(ch + 1);
            cp_wait<1>();
        } else {
            cp_wait<0>();
        }
        __syncthreads();
        uint32_t st = sbase + (uint32_t)(ch & 1) * STGSZ;
#pragma unroll
        for (int k16 = 0; k16 < 2; k16++) {
            uint32_t coff = (uint32_t)(k16 * 32 + (lane >> 4) * 16);
            uint32_t arow = (uint32_t)(w * 16 + (lane & 15)) * 80;
            uint32_t ah[4], al[4];
            ldsm4(ah[0], ah[1], ah[2], ah[3], st + arow + coff);
            ldsm4(al[0], al[1], al[2], al[3], st + 10240 + arow + coff);
#pragma unroll
            for (int nh = 0; nh < 8; nh++) {
                uint32_t brow = (uint32_t)(nh * 16 + (lane & 15)) * 80;
                uint32_t r0, r1, r2, r3;
                uint32_t bh0[2], bh1[2], bl0[2], bl1[2];
                ldsm4(r0, r1, r2, r3, st + 20480 + brow + coff);
                bh0[0] = r0; bh0[1] = r2; bh1[0] = r1; bh1[1] = r3;
                ldsm4(r0, r1, r2, r3, st + 30720 + brow + coff);
                bl0[0] = r0; bl0[1] = r2; bl1[0] = r1; bl1[1] = r3;
                mma16816(acc[2 * nh], ah, bh0);
                mma16816(acc[2 * nh + 1], ah, bh1);
                mma16816(acc[2 * nh], ah, bl0);
                mma16816(acc[2 * nh + 1], ah, bl1);
                mma16816(acc[2 * nh], al, bh0);
                mma16816(acc[2 * nh + 1], al, bh1);
            }
        }
        __syncthreads();
    }

    // bias + hi/lo split, pack into A-fragments (C->A identity)
    uint32_t th_hi[8][4], th_lo[8][4];
    {
        int t2 = (lane & 3) * 2;
#pragma unroll
        for (int s = 0; s < 8; s++) {
#pragma unroll
            for (int half2i = 0; half2i < 2; half2i++) {
                int nb = 2 * s + half2i;
                float b0 = bth[8 * nb + t2], b1 = bth[8 * nb + t2 + 1];
                float x0 = acc[nb][0] + b0, x1 = acc[nb][1] + b1;
                float x2 = acc[nb][2] + b0, x3 = acc[nb][3] + b1;
                __half hx0 = __float2half_rn(x0), hx1 = __float2half_rn(x1);
                __half hx2 = __float2half_rn(x2), hx3 = __float2half_rn(x3);
                th_hi[s][2 * half2i + 0] = ((uint32_t)*(uint16_t*)&hx1 << 16) | *(uint16_t*)&hx0;
                th_hi[s][2 * half2i + 1] = ((uint32_t)*(uint16_t*)&hx3 << 16) | *(uint16_t*)&hx2;
                th_lo[s][2 * half2i + 0] = pkh2(x0 - __half2float(hx0), x1 - __half2float(hx1));
                th_lo[s][2 * half2i + 1] = pkh2(x2 - __half2float(hx2), x3 - __half2float(hx3));
            }
        }
    }
    __syncthreads();

    // ======== MAIN LOOP ========
    auto load_stage = [&](int mt) {
        uint32_t st = sbase + (uint32_t)(mt & 1) * STGSZ;
        int m0 = mt * 64;
#pragma unroll
        for (int t = 0; t < 4; t++) {
            int idx = tid + t * 256;
            int row = idx >> 4, j = idx & 15;
            uint32_t d = st + (uint32_t)(j >> 2) * 5120 + row * 80 + (j & 3) * 16;
            size_t go = (size_t)(m0 + row) * CHI + j * 8;
            cp16(d, pb_hi + go);
            cp16(d + 20480, pb_lo + go);
        }
#pragma unroll
        for (int t = 0; t < 4; t++) {
            int idx = tid + t * 256;
            int row = idx >> 3, j = idx & 7;
            uint32_t d = st + 40960 + (uint32_t)(j >> 2) * 10240 + row * 80 + (j & 3) * 16;
            cp16(d, gb + (size_t)row * MPOOL + m0 + j * 8);
        }
        cp_commit();
    };
    load_stage(0);

    float yacc[16][4];
#pragma unroll
    for (int j = 0; j < 16; j++)
#pragma unroll
        for (int e = 0; e < 4; e++) yacc[j][e] = 0.f;
    float rmax0 = -1e30f, rmax1 = -1e30f, rsum0 = 0.f, rsum1 = 0.f;

    for (int mt = 0; mt < 16; mt++) {
        if (mt + 1 < 16) {
            load_stage(mt + 1);
            cp_wait<1>();
        } else {
            cp_wait<0>();
        }
        __syncthreads();
        uint32_t st = sbase + (uint32_t)(mt & 1) * STGSZ;

        // ---- S = theta . phi^T (3-pass split, theta from registers) ----
        float sacc[8][4];
#pragma unroll
        for (int j = 0; j < 8; j++)
#pragma unroll
            for (int e = 0; e < 4; e++) sacc[j][e] = 0.f;

#pragma unroll
        for (int s = 0; s < 8; s++) {
            uint32_t chunk = (uint32_t)(s >> 1);
            uint32_t inner = (uint32_t)((s & 1) * 32 + (lane >> 4) * 16);
#pragma unroll
            for (int p = 0; p < 4; p++) {
                uint32_t brow = (uint32_t)(p * 16 + (lane & 15)) * 80;
                uint32_t bad = st + chunk * 5120 + brow + inner;
                uint32_t r0, r1, r2, r3;
                uint32_t bh0[2], bh1[2], bl0[2], bl1[2];
                ldsm4(r0, r1, r2, r3, bad);
                bh0[0] = r0; bh0[1] = r2; bh1[0] = r1; bh1[1] = r3;
                ldsm4(r0, r1, r2, r3, bad + 20480);
                bl0[0] = r0; bl0[1] = r2; bl1[0] = r1; bl1[1] = r3;
                mma16816(sacc[2 * p], th_hi[s], bh0);
                mma16816(sacc[2 * p + 1], th_hi[s], bh1);
                mma16816(sacc[2 * p], th_hi[s], bl0);
                mma16816(sacc[2 * p + 1], th_hi[s], bl1);
                mma16816(sacc[2 * p], th_lo[s], bh0);
                mma16816(sacc[2 * p + 1], th_lo[s], bh1);
            }
        }

        // ---- online softmax (rows r, r+8 per thread) ----
        float tm0 = -1e30f, tm1 = -1e30f;
#pragma unroll
        for (int j = 0; j < 8; j++) {
            tm0 = fmaxf(tm0, fmaxf(sacc[j][0], sacc[j][1]));
            tm1 = fmaxf(tm1, fmaxf(sacc[j][2], sacc[j][3]));
        }
        tm0 = fmaxf(tm0, __shfl_xor_sync(0xffffffffu, tm0, 1));
        tm0 = fmaxf(tm0, __shfl_xor_sync(0xffffffffu, tm0, 2));
        tm1 = fmaxf(tm1, __shfl_xor_sync(0xffffffffu, tm1, 1));
        tm1 = fmaxf(tm1, __shfl_xor_sync(0xffffffffu, tm1, 2));
        float mn0 = fmaxf(rmax0, tm0), mn1 = fmaxf(rmax1, tm1);
        float sc0 = __expf(rmax0 - mn0), sc1 = __expf(rmax1 - mn1);
        float ts0 = 0.f, ts1 = 0.f;
#pragma unroll
        for (int j = 0; j < 8; j++) {
            sacc[j][0] = __expf(sacc[j][0] - mn0);
            sacc[j][1] = __expf(sacc[j][1] - mn0);
            sacc[j][2] = __expf(sacc[j][2] - mn1);
            sacc[j][3] = __expf(sacc[j][3] - mn1);
            ts0 += sacc[j][0] + sacc[j][1];
            ts1 += sacc[j][2] + sacc[j][3];
        }
        ts0 += __shfl_xor_sync(0xffffffffu, ts0, 1);
        ts0 += __shfl_xor_sync(0xffffffffu, ts0, 2);
        ts1 += __shfl_xor_sync(0xffffffffu, ts1, 1);
        ts1 += __shfl_xor_sync(0xffffffffu, ts1, 2);
        rsum0 = rsum0 * sc0 + ts0;
        rsum1 = rsum1 * sc1 + ts1;
        rmax0 = mn0; rmax1 = mn1;
#pragma unroll
        for (int j = 0; j < 16; j++) {
            yacc[j][0] *= sc0; yacc[j][1] *= sc0;
            yacc[j][2] *= sc1; yacc[j][3] *= sc1;
        }

        // ---- pack P into A-frags ----
        uint32_t pf[4][4];
#pragma unroll
        for (int s2 = 0; s2 < 4; s2++) {
            pf[s2][0] = pkh2(sacc[2 * s2][0], sacc[2 * s2][1]);
            pf[s2][1] = pkh2(sacc[2 * s2][2], sacc[2 * s2][3]);
            pf[s2][2] = pkh2(sacc[2 * s2 + 1][0], sacc[2 * s2 + 1][1]);
            pf[s2][3] = pkh2(sacc[2 * s2 + 1][2], sacc[2 * s2 + 1][3]);
        }

        // ---- y += P . g ----
#pragma unroll
        for (int s2 = 0; s2 < 4; s2++) {
            uint32_t chunk = (uint32_t)(s2 >> 1);
            uint32_t inner = (uint32_t)((s2 & 1) * 32 + (lane >> 4) * 16);
#pragma unroll
            for (int pc = 0; pc < 8; pc++) {
                uint32_t brow = (uint32_t)(pc * 16 + (lane & 15)) * 80;
                uint32_t r0, r1, r2, r3;
                ldsm4(r0, r1, r2, r3, st + 40960 + chunk * 10240 + brow + inner);
                uint32_t bb0[2] = {r0, r2};
                uint32_t bb1[2] = {r1, r3};
                mma16816(yacc[2 * pc], pf[s2], bb0);
                mma16816(yacc[2 * pc + 1], pf[s2], bb1);
            }
        }
        __syncthreads();
    }

    // ---- normalize + write y fp16 [n][ci] ----
    float inv0 = 1.f / rsum0, inv1 = 1.f / rsum1;
    int r = lane >> 2, c2 = (lane & 3) * 2;
    size_t rowbase = (size_t)b * NPIX + n0 + w * 16;
#pragma unroll
    for (int j = 0; j < 16; j++) {
        int col = j * 8 + c2;
        uint32_t v0 = pkh2(yacc[j][0] * inv0, yacc[j][1] * inv0);
        uint32_t v1 = pkh2(yacc[j][2] * inv1, yacc[j][3] * inv1);
        *(uint32_t*)(Y + (rowbase + r) * CHI + col) = v0;
        *(uint32_t*)(Y + (rowbase + r + 8) * CHI + col) = v1;
    }
}

// ---------------- weight prep: fp32 -> fp16 hi/lo + BN constants ----------------
__global__ void wprep_kernel(const float* __restrict__ Wth, const float* __restrict__ Wph,
                             const float* __restrict__ Wg, const float* __restrict__ Ww,
                             const float* __restrict__ gamma, const float* __restrict__ beta,
                             const float* __restrict__ mean, const float* __restrict__ var,
                             const float* __restrict__ bw) {
    int i = blockIdx.x * 256 + threadIdx.x;
    float a = Wth[i];
    __half h = __float2half_rn(a);
    h_Wth_hi[i] = h;
    h_Wth_lo[i] = __float2half_rn(a - __half2float(h));
    float b = Wph[i];
    __half hb = __float2half_rn(b);
    h_Wph_hi[i] = hb;
    h_Wph_lo[i] = __float2half_rn(b - __half2float(hb));
    h_Wg_hi[i] = __float2half_rn(Wg[i]);
    h_Ww_hi[i] = __float2half_rn(Ww[i]);
    if (i < CC) {
        float sc = gamma[i] * rsqrtf(var[i] + 1e-5f);
        g_bns[i] = sc;
        g_bnt[i] = beta[i] + (bw[i] - mean[i]) * sc;
    }
}

// ---------------- pool(2x2) + transpose -> fp16 [m][c] ----------------
__global__ void __launch_bounds__(256) pooltrans_kernel(const float* __restrict__ q,
                                                        const float* __restrict__ v) {
    __shared__ float ts[32][33];
    int z = blockIdx.z;
    bool isq = (z < BB);
    const float* src = isq ? q : v;
    int b = z & (BB - 1);
    int m0 = blockIdx.x * 32, c0 = blockIdx.y * 32;
    int tx = threadIdx.x, ty = threadIdx.y;
    const float* sb = src + (size_t)b * CC * NPIX;
    int m = m0 + tx, mi = m >> 5, mj = m & 31;
#pragma unroll
    for (int i = 0; i < 4; i++) {
        int c = c0 + ty + i * 8;
        const float* p = sb + (size_t)c * NPIX + (2 * mi) * WW + 2 * mj;
        ts[ty + i * 8][tx] = 0.25f * (p[0] + p[1] + p[WW] + p[WW + 1]);
    }
    __syncthreads();
    size_t base = (size_t)b * MPOOL * CC;
#pragma unroll
    for (int i = 0; i < 4; i++) {
        float val = ts[tx][ty + i * 8];
        size_t idx = base + (size_t)(m0 + ty + i * 8) * CC + c0 + tx;
        __half h = __float2half_rn(val);
        if (isq) {
            h_pq_hi[idx] = h;
            h_pq_lo[idx] = __float2half_rn(val - __half2float(h));
        } else {
            h_pv_hi[idx] = h;
        }
    }
}

// ---------------- transpose k: [c][n] -> fp16 hi/lo [n][c] ----------------
__global__ void __launch_bounds__(256) transk_kernel(const float* __restrict__ k) {
    __shared__ float ts[32][33];
    int b = blockIdx.z;
    int n0 = blockIdx.x * 32, c0 = blockIdx.y * 32;
    int tx = threadIdx.x, ty = threadIdx.y;
    const float* sb = k + (size_t)b * CC * NPIX;
#pragma unroll
    for (int i = 0; i < 4; i++)
        ts[ty + i * 8][tx] = sb[(size_t)(c0 + ty + i * 8) * NPIX + n0 + tx];
    __syncthreads();
    size_t base = (size_t)b * NPIX * CC;
#pragma unroll
    for (int i = 0; i < 4; i++) {
        float val = ts[tx][ty + i * 8];
        size_t idx = base + (size_t)(n0 + ty + i * 8) * CC + c0 + tx;
        __half h = __float2half_rn(val);
        h_kT_hi[idx] = h;
        h_kT_lo[idx] = __float2half_rn(val - __half2float(h));
    }
}

// ---------------- launch ----------------
extern "C" void kernel_launch(void* const* d_in, const int* in_sizes, int n_in,
                              void* d_out, int out_size) {
    (void)in_sizes; (void)n_in; (void)out_size;
    const float* q     = (const float*)d_in[0];
    const float* k     = (const float*)d_in[1];
    const float* v     = (const float*)d_in[2];
    const float* Wg    = (const float*)d_in[3];
    const float* bg    = (const float*)d_in[4];
    const float* Wth   = (const float*)d_in[5];
    const float* bth   = (const float*)d_in[6];
    const float* Wph   = (const float*)d_in[7];
    const float* bph   = (const float*)d_in[8];
    const float* Ww    = (const float*)d_in[9];
    const float* bw    = (const float*)d_in[10];
    const float* gamma = (const float*)d_in[11];
    const float* beta  = (const float*)d_in[12];
    const float* mean  = (const float*)d_in[13];
    const float* var   = (const float*)d_in[14];
    float* out = (float*)d_out;

    __half *kThi, *kTlo, *pqhi, *pqlo, *pvhi;
    __half *Wthhi, *Wthlo, *Wphhi, *Wphlo, *Wghi, *Wwhi;
    __half *phhi, *phlo, *gmat, *y;
    cudaGetSymbolAddress((void**)&kThi, h_kT_hi);
    cudaGetSymbolAddress((void**)&kTlo, h_kT_lo);
    cudaGetSymbolAddress((void**)&pqhi, h_pq_hi);
    cudaGetSymbolAddress((void**)&pqlo, h_pq_lo);
    cudaGetSymbolAddress((void**)&pvhi, h_pv_hi);
    cudaGetSymbolAddress((void**)&Wthhi, h_Wth_hi);
    cudaGetSymbolAddress((void**)&Wthlo, h_Wth_lo);
    cudaGetSymbolAddress((void**)&Wphhi, h_Wph_hi);
    cudaGetSymbolAddress((void**)&Wphlo, h_Wph_lo);
    cudaGetSymbolAddress((void**)&Wghi, h_Wg_hi);
    cudaGetSymbolAddress((void**)&Wwhi, h_Ww_hi);
    cudaGetSymbolAddress((void**)&phhi, h_ph_hi);
    cudaGetSymbolAddress((void**)&phlo, h_ph_lo);
    cudaGetSymbolAddress((void**)&gmat, h_g);
    cudaGetSymbolAddress((void**)&y, h_y);

    const int SMS = 81920;   // split hgemm: 2 stages x 40KB
    const int SMN = 40960;   // plain hgemm: 2 stages x 20KB
    const int SMF = 122880;  // flash: 2 stages x 60KB
    cudaFuncSetAttribute(hgemm<256, true, 1>, cudaFuncAttributeMaxDynamicSharedMemorySize, SMS);
    cudaFuncSetAttribute(hgemm<256, false, 2>, cudaFuncAttributeMaxDynamicSharedMemorySize, SMN);
    cudaFuncSetAttribute(hgemm<128, false, 4>, cudaFuncAttributeMaxDynamicSharedMemorySize, SMN);
    cudaFuncSetAttribute(flash_kernel, cudaFuncAttributeMaxDynamicSharedMemorySize, SMF);

    // 1) prep
    wprep_kernel<<<CHI * CC / 256, 256>>>(Wth, Wph, Wg, Ww, gamma, beta, mean, var, bw);
    pooltrans_kernel<<<dim3(MPOOL / 32, CC / 32, 2 * BB), dim3(32, 8)>>>(q, v);
    transk_kernel<<<dim3(NPIX / 32, CC / 32, BB), dim3(32, 8)>>>(k);

    // 2) phi[m][ci] = pq[m][c] . Wph[ci][c]  (split, +bph, split-write)
    hgemm<256, true, 1><<<dim3(1, MPOOL / 128, BB), 256, SMS>>>(
        pqhi, pqlo, Wphhi, Wphlo, nullptr, phhi, phlo,
        (size_t)MPOOL * CC, 0, (size_t)MPOOL * CHI, CHI, bph, nullptr, 0, 0);
    // 3) g[ci][m] = Wg[ci][c] . pv[m][c]  (+bg[row], fp16)
    hgemm<256, false, 2><<<dim3(MPOOL / 128, 1, BB), 256, SMN>>>(
        Wghi, nullptr, pvhi, nullptr, nullptr, gmat, nullptr,
        0, (size_t)MPOOL * CC, (size_t)CHI * MPOOL, MPOOL, bg, nullptr, 0, 0);
    // 4) fused: theta-projection + S -> softmax -> y
    flash_kernel<<<dim3(NPIX / 128, BB), 256, SMF>>>(
        kThi, kTlo, Wthhi, Wthlo, bth, phhi, phlo, gmat, y);
    // 5) out[co][n] = BN(Ww[co][ci] . y[n][ci]) + v[co][n]
    hgemm<128, false, 4><<<dim3(NPIX / 128, CC / 128, BB), 256, SMN>>>(
        Wwhi, nullptr, y, nullptr, out, nullptr, nullptr,
        0, (size_t)NPIX * CHI, (size_t)CC * NPIX, NPIX,
        nullptr, v, (size_t)CC * NPIX, NPIX);
}

// round 7
// speedup vs baseline: 3.2324x; 1.1198x over previous
#include <cuda_runtime.h>
#include <cuda_fp16.h>
#include <cstdint>
#include <cstddef>

// Problem dims
#define BB   8
#define CC   256
#define CHI  128
#define HH   64
#define WW   64
#define NPIX 4096   // H*W
#define MPOOL 1024  // (H/2)*(W/2)

// ---------------- gmem "smem-image" buffers (no allocations allowed) ----------------
// Region layouts (bytes): a "chunk" is 32 K-halves per row, row stride 80B.
//   lane_off(r, c<32) = r*80 + (c>>3)*16 + (c&7)*2
// kimg   : per (b, ntile32, chunk8) 20480 = [kT_hi 128x80 | kT_lo 128x80]
// wthimg : per chunk8 20480 = [Wth_hi 128x80 | Wth_lo]
// wphimg : per chunk8 20480 = [Wph_hi | Wph_lo]
// wgimg  : per chunk8 10240 = Wg_hi 128x80
// wwimg  : per (rowtile2, chunk4) 10240 = Ww_hi 128x80
// pqimg  : per (b, mtile8, chunk8) 20480 = [pq_hi 128x80 | pq_lo]
// pvimg  : per (b, mtile8, chunk8) 10240 = pv_hi 128x80
// pgimg  : per (b, mt16) 61440 = [phi_hi 4ch x 64x80 | phi_lo | g 2ch x 128x80]
// yimg   : per (b, ntile32, chunk4) 10240 = y 128x80
__device__ __align__(128) char g_kimg[(size_t)8 * 32 * 8 * 20480];
__device__ __align__(128) char g_wthimg[8 * 20480];
__device__ __align__(128) char g_wphimg[8 * 20480];
__device__ __align__(128) char g_wgimg[8 * 10240];
__device__ __align__(128) char g_wwimg[8 * 10240];
__device__ __align__(128) char g_pqimg[(size_t)8 * 8 * 8 * 20480];
__device__ __align__(128) char g_pvimg[(size_t)8 * 8 * 8 * 10240];
__device__ __align__(128) char g_pgimg[(size_t)8 * 16 * 61440];
__device__ __align__(128) char g_yimg[(size_t)8 * 32 * 4 * 10240];
__device__ float g_bns[CC];
__device__ float g_bnt[CC];

// ---------------- PTX helpers ----------------
__device__ __forceinline__ uint32_t smem_u32(const void* p) {
    uint32_t a;
    asm("{ .reg .u64 t; cvta.to.shared.u64 t, %1; cvt.u32.u64 %0, t; }" : "=r"(a) : "l"(p));
    return a;
}
__device__ __forceinline__ void cpbulk(uint32_t dst, const void* src, uint32_t bytes,
                                       uint32_t mbar) {
    asm volatile(
        "cp.async.bulk.shared::cluster.global.mbarrier::complete_tx::bytes [%0], [%1], %2, [%3];"
        :: "r"(dst), "l"(src), "r"(bytes), "r"(mbar) : "memory");
}
#define MBAR_INIT(mb, n) \
    asm volatile("mbarrier.init.shared.b64 [%0], %1;" :: "r"(mb), "r"((uint32_t)(n)) : "memory")
#define MBAR_EXPECT(mb, n) \
    asm volatile("mbarrier.arrive.expect_tx.shared.b64 _, [%0], %1;" :: "r"(mb), "r"((uint32_t)(n)) : "memory")

__device__ __forceinline__ void mbar_wait(uint32_t mb, uint32_t parity) {
    uint32_t done;
    asm volatile(
        "{\n\t.reg .pred p;\n\t"
        "mbarrier.try_wait.parity.acquire.cta.shared::cta.b64 p, [%1], %2;\n\t"
        "selp.b32 %0, 1, 0, p;\n\t}"
        : "=r"(done) : "r"(mb), "r"(parity) : "memory");
    if (!done) {
        asm volatile(
            "{\n\t.reg .pred P1;\n\t"
            "W0_%=:\n\t"
            "mbarrier.try_wait.parity.acquire.cta.shared::cta.b64 P1, [%0], %1, 0x989680;\n\t"
            "@P1 bra.uni W1_%=;\n\t"
            "bra.uni W0_%=;\n\t"
            "W1_%=:\n\t}"
            :: "r"(mb), "r"(parity) : "memory");
    }
}
__device__ __forceinline__ void ldsm4(uint32_t& r0, uint32_t& r1, uint32_t& r2, uint32_t& r3,
                                      uint32_t a) {
    asm volatile("ldmatrix.sync.aligned.m8n8.x4.shared.b16 {%0,%1,%2,%3}, [%4];"
                 : "=r"(r0), "=r"(r1), "=r"(r2), "=r"(r3) : "r"(a));
}
__device__ __forceinline__ void mma16816(float* c, const uint32_t* a, const uint32_t* b) {
    asm volatile(
        "mma.sync.aligned.m16n8k16.row.col.f32.f16.f16.f32 "
        "{%0,%1,%2,%3}, {%4,%5,%6,%7}, {%8,%9}, {%0,%1,%2,%3};"
        : "+f"(c[0]), "+f"(c[1]), "+f"(c[2]), "+f"(c[3])
        : "r"(a[0]), "r"(a[1]), "r"(a[2]), "r"(a[3]), "r"(b[0]), "r"(b[1]));
}
__device__ __forceinline__ uint32_t pkh2(float a, float b) {
    __half2 h = __floats2half2_rn(a, b);
    return *(uint32_t*)&h;
}
__device__ __forceinline__ uint32_t lane_off(int r, int c) {  // c in [0,32)
    return (uint32_t)(r * 80 + (c >> 3) * 16 + (c & 7) * 2);
}

// ---------------- bulk-fed tensor-core GEMM ----------------
// C[row][col] = sum_k A[row][k].B[col][k], operands pre-staged as smem images.
// EPI 5: phi -> pgimg (col bias, split hi/lo)
// EPI 6: g   -> pgimg (row bias, fp16)
// EPI 4: final -> fp32 out with BN(row)+resid
template <int NCH, bool SPLIT, int EPI>
__global__ void __launch_bounds__(256, 1) hgemmB(
    const char* __restrict__ Aimg, const char* __restrict__ Bimg,
    int aZ, int aY, int aX, int bZ, int bY, int bX,
    const float* __restrict__ bias,
    char* __restrict__ outImg, float* __restrict__ outF,
    const float* __restrict__ resid) {
    constexpr uint32_t REG = SPLIT ? 20480 : 10240;
    constexpr uint32_t STAGE = SPLIT ? 40960 : 20480;
    extern __shared__ char sm[];
    __shared__ __align__(8) uint64_t s_mbar[2];
    uint32_t sbase = smem_u32(sm);
    uint32_t mb0 = smem_u32(&s_mbar[0]);

    int tid = threadIdx.x, lane = tid & 31, w = tid >> 5;
    int wm = w >> 2, wn = w & 3;
    int z = blockIdx.z, by = blockIdx.y, bx = blockIdx.x;
    const char* Ab = Aimg + (size_t)(z * aZ + by * aY + bx * aX) * (NCH * REG);
    const char* Bb = Bimg + (size_t)(z * bZ + by * bY + bx * bX) * (NCH * REG);

    if (tid == 0) { MBAR_INIT(mb0, 1); MBAR_INIT(mb0 + 8, 1); }
    __syncthreads();

    auto issue = [&](int ch) {
        uint32_t st = sbase + (uint32_t)(ch & 1) * STAGE;
        uint32_t mb = mb0 + (uint32_t)(ch & 1) * 8;
        MBAR_EXPECT(mb, SPLIT ? 40960u : 20480u);
        if (SPLIT) {
            cpbulk(st, Ab + (size_t)ch * REG, 10240, mb);
            cpbulk(st + 20480, Ab + (size_t)ch * REG + 10240, 10240, mb);
            cpbulk(st + 10240, Bb + (size_t)ch * REG, 10240, mb);
            cpbulk(st + 30720, Bb + (size_t)ch * REG + 10240, 10240, mb);
        } else {
            cpbulk(st, Ab + (size_t)ch * REG, 10240, mb);
            cpbulk(st + 10240, Bb + (size_t)ch * REG, 10240, mb);
        }
    };
    if (tid == 0) { issue(0); issue(1); }

    float acc[4][4][4];
#pragma unroll
    for (int i = 0; i < 4; i++)
#pragma unroll
        for (int j = 0; j < 4; j++)
#pragma unroll
            for (int e = 0; e < 4; e++) acc[i][j][e] = 0.f;

    for (int ch = 0; ch < NCH; ch++) {
        mbar_wait(mb0 + (uint32_t)(ch & 1) * 8, (uint32_t)((ch >> 1) & 1));
        uint32_t sa = sbase + (uint32_t)(ch & 1) * STAGE;
        uint32_t sb = sa + 10240;
#pragma unroll
        for (int k16 = 0; k16 < 2; k16++) {
            uint32_t a[4][4], b[4][2];
            uint32_t coff = (uint32_t)(k16 * 32 + (lane >> 4) * 16);
#pragma unroll
            for (int mi = 0; mi < 4; mi++) {
                uint32_t ad = sa + (uint32_t)(wm * 64 + mi * 16 + (lane & 15)) * 80 + coff;
                ldsm4(a[mi][0], a[mi][1], a[mi][2], a[mi][3], ad);
            }
#pragma unroll
            for (int nh = 0; nh < 2; nh++) {
                uint32_t bd = sb + (uint32_t)(wn * 32 + nh * 16 + (lane & 15)) * 80 + coff;
                uint32_t r0, r1, r2, r3;
                ldsm4(r0, r1, r2, r3, bd);
                b[nh * 2 + 0][0] = r0; b[nh * 2 + 0][1] = r2;
                b[nh * 2 + 1][0] = r1; b[nh * 2 + 1][1] = r3;
            }
#pragma unroll
            for (int mi = 0; mi < 4; mi++)
#pragma unroll
                for (int ni = 0; ni < 4; ni++) mma16816(acc[mi][ni], a[mi], b[ni]);
            if (SPLIT) {
                uint32_t al[4][4], bl[4][2];
#pragma unroll
                for (int mi = 0; mi < 4; mi++) {
                    uint32_t ad = sa + 20480 + (uint32_t)(wm * 64 + mi * 16 + (lane & 15)) * 80 + coff;
                    ldsm4(al[mi][0], al[mi][1], al[mi][2], al[mi][3], ad);
                }
#pragma unroll
                for (int nh = 0; nh < 2; nh++) {
                    uint32_t bd = sa + 30720 + (uint32_t)(wn * 32 + nh * 16 + (lane & 15)) * 80 + coff;
                    uint32_t r0, r1, r2, r3;
                    ldsm4(r0, r1, r2, r3, bd);
                    bl[nh * 2 + 0][0] = r0; bl[nh * 2 + 0][1] = r2;
                    bl[nh * 2 + 1][0] = r1; bl[nh * 2 + 1][1] = r3;
                }
#pragma unroll
                for (int mi = 0; mi < 4; mi++)
#pragma unroll
                    for (int ni = 0; ni < 4; ni++) {
                        mma16816(acc[mi][ni], a[mi], bl[ni]);
                        mma16816(acc[mi][ni], al[mi], b[ni]);
                    }
            }
        }
        __syncthreads();
        if (tid == 0 && ch + 2 < NCH) issue(ch + 2);
    }

    // ---------------- epilogue ----------------
    int r = lane >> 2, cp2 = (lane & 3) * 2;
    int row0 = by * 128 + wm * 64;
    int col0 = bx * 128 + wn * 32;
#pragma unroll
    for (int mi = 0; mi < 4; mi++) {
#pragma unroll
        for (int h = 0; h < 2; h++) {
            int row = row0 + mi * 16 + h * 8 + r;
            float s = 1.f, t = 0.f;
            if (EPI == 6) t = bias[row];
            if (EPI == 4) { s = g_bns[row]; t = g_bnt[row]; }
#pragma unroll
            for (int ni = 0; ni < 4; ni++) {
                int col = col0 + ni * 8 + cp2;
                float v0 = acc[mi][ni][h * 2 + 0];
                float v1 = acc[mi][ni][h * 2 + 1];
                if (EPI == 5) {
                    v0 += bias[col]; v1 += bias[col + 1];
                    __half h0 = __float2half_rn(v0), h1 = __float2half_rn(v1);
                    uint32_t hi = ((uint32_t)*(uint16_t*)&h1 << 16) | *(uint16_t*)&h0;
                    uint32_t lo = pkh2(v0 - __half2float(h0), v1 - __half2float(h1));
                    char* base = outImg + (size_t)(z * 16 + (row >> 6)) * 61440;
                    uint32_t off = (uint32_t)(col >> 5) * 5120 + lane_off(row & 63, col & 31);
                    *(uint32_t*)(base + off) = hi;
                    *(uint32_t*)(base + off + 20480) = lo;
                } else if (EPI == 6) {
                    uint32_t hv = pkh2(v0 + t, v1 + t);
                    char* base = outImg + (size_t)(z * 16 + (col >> 6)) * 61440 + 40960;
                    uint32_t off = (uint32_t)((col >> 5) & 1) * 10240 + lane_off(row, col & 31);
                    *(uint32_t*)(base + off) = hv;
                } else {  // EPI 4
                    const float* rp = resid + (size_t)z * CC * NPIX + (size_t)row * NPIX + col;
                    float* op = outF + (size_t)z * CC * NPIX + (size_t)row * NPIX + col;
                    op[0] = v0 * s + t + rp[0];
                    op[1] = v1 * s + t + rp[1];
                }
            }
        }
    }
}

// ---------------- fused flash: theta prologue (bulk) + S-softmax-y loop (bulk) ----------------
__global__ void __launch_bounds__(256, 1) flash_kernel(const float* __restrict__ bth) {
    extern __shared__ char sm[];
    __shared__ __align__(8) uint64_t s_mbar[2];
    uint32_t sbase = smem_u32(sm);
    uint32_t mb0 = smem_u32(&s_mbar[0]);
    const uint32_t STGSZ = 61440;

    int tid = threadIdx.x, lane = tid & 31, w = tid >> 5;
    int b = blockIdx.y;
    int nt = blockIdx.x;  // n-tile (128 rows)
    const char* kimgT = g_kimg + (size_t)(b * 32 + nt) * 8 * 20480;
    const char* pgB = g_pgimg + (size_t)b * 16 * 61440;

    if (tid == 0) { MBAR_INIT(mb0, 1); MBAR_INIT(mb0 + 8, 1); }
    __syncthreads();

    auto issueP = [&](int ch) {
        uint32_t st = sbase + (uint32_t)(ch & 1) * STGSZ;
        uint32_t mb = mb0 + (uint32_t)(ch & 1) * 8;
        MBAR_EXPECT(mb, 40960u);
        cpbulk(st, kimgT + (size_t)ch * 20480, 20480, mb);
        cpbulk(st + 20480, g_wthimg + (size_t)ch * 20480, 20480, mb);
    };
    auto issueM = [&](int mt) {
        uint32_t st = sbase + (uint32_t)(mt & 1) * STGSZ;
        uint32_t mb = mb0 + (uint32_t)(mt & 1) * 8;
        MBAR_EXPECT(mb, 61440u);
        cpbulk(st, pgB + (size_t)mt * 61440, 61440, mb);
    };
    if (tid == 0) { issueP(0); issueP(1); }

    // ======== PROLOGUE: theta = kT.Wth^T (3-pass split), 8 chunks of K=32 ========
    float acc[16][4];
#pragma unroll
    for (int j = 0; j < 16; j++)
#pragma unroll
        for (int e = 0; e < 4; e++) acc[j][e] = 0.f;

    for (int ch = 0; ch < 8; ch++) {
        mbar_wait(mb0 + (uint32_t)(ch & 1) * 8, (uint32_t)((ch >> 1) & 1));
        uint32_t st = sbase + (uint32_t)(ch & 1) * STGSZ;
#pragma unroll
        for (int k16 = 0; k16 < 2; k16++) {
            uint32_t coff = (uint32_t)(k16 * 32 + (lane >> 4) * 16);
            uint32_t arow = (uint32_t)(w * 16 + (lane & 15)) * 80;
            uint32_t ah[4], al[4];
            ldsm4(ah[0], ah[1], ah[2], ah[3], st + arow + coff);
            ldsm4(al[0], al[1], al[2], al[3], st + 10240 + arow + coff);
#pragma unroll
            for (int nh = 0; nh < 8; nh++) {
                uint32_t brow = (uint32_t)(nh * 16 + (lane & 15)) * 80;
                uint32_t r0, r1, r2, r3;
                uint32_t bh0[2], bh1[2], bl0[2], bl1[2];
                ldsm4(r0, r1, r2, r3, st + 20480 + brow + coff);
                bh0[0] = r0; bh0[1] = r2; bh1[0] = r1; bh1[1] = r3;
                ldsm4(r0, r1, r2, r3, st + 30720 + brow + coff);
                bl0[0] = r0; bl0[1] = r2; bl1[0] = r1; bl1[1] = r3;
                mma16816(acc[2 * nh], ah, bh0);
                mma16816(acc[2 * nh + 1], ah, bh1);
                mma16816(acc[2 * nh], ah, bl0);
                mma16816(acc[2 * nh + 1], ah, bl1);
                mma16816(acc[2 * nh], al, bh0);
                mma16816(acc[2 * nh + 1], al, bh1);
            }
        }
        __syncthreads();
        if (tid == 0) {
            if (ch + 2 < 8) issueP(ch + 2);
            else if (ch == 6) issueM(0);
            else issueM(1);
        }
    }

    // bias + hi/lo split, pack into A-fragments
    uint32_t th_hi[8][4], th_lo[8][4];
    {
        int t2 = (lane & 3) * 2;
#pragma unroll
        for (int s = 0; s < 8; s++) {
#pragma unroll
            for (int hf = 0; hf < 2; hf++) {
                int nb = 2 * s + hf;
                float b0 = bth[8 * nb + t2], b1 = bth[8 * nb + t2 + 1];
                float x0 = acc[nb][0] + b0, x1 = acc[nb][1] + b1;
                float x2 = acc[nb][2] + b0, x3 = acc[nb][3] + b1;
                __half hx0 = __float2half_rn(x0), hx1 = __float2half_rn(x1);
                __half hx2 = __float2half_rn(x2), hx3 = __float2half_rn(x3);
                th_hi[s][2 * hf + 0] = ((uint32_t)*(uint16_t*)&hx1 << 16) | *(uint16_t*)&hx0;
                th_hi[s][2 * hf + 1] = ((uint32_t)*(uint16_t*)&hx3 << 16) | *(uint16_t*)&hx2;
                th_lo[s][2 * hf + 0] = pkh2(x0 - __half2float(hx0), x1 - __half2float(hx1));
                th_lo[s][2 * hf + 1] = pkh2(x2 - __half2float(hx2), x3 - __half2float(hx3));
            }
        }
    }

    // ======== MAIN LOOP ========
    float yacc[16][4];
#pragma unroll
    for (int j = 0; j < 16; j++)
#pragma unroll
        for (int e = 0; e < 4; e++) yacc[j][e] = 0.f;
    float rmax0 = -1e30f, rmax1 = -1e30f, rsum0 = 0.f, rsum1 = 0.f;

    for (int mt = 0; mt < 16; mt++) {
        mbar_wait(mb0 + (uint32_t)(mt & 1) * 8, (uint32_t)((mt >> 1) & 1));
        uint32_t st = sbase + (uint32_t)(mt & 1) * STGSZ;

        // ---- S = theta.phi^T (3-pass split, theta from regs) ----
        float sacc[8][4];
#pragma unroll
        for (int j = 0; j < 8; j++)
#pragma unroll
            for (int e = 0; e < 4; e++) sacc[j][e] = 0.f;

#pragma unroll
        for (int s = 0; s < 8; s++) {
            uint32_t chunk = (uint32_t)(s >> 1);
            uint32_t inner = (uint32_t)((s & 1) * 32 + (lane >> 4) * 16);
#pragma unroll
            for (int p = 0; p < 4; p++) {
                uint32_t brow = (uint32_t)(p * 16 + (lane & 15)) * 80;
                uint32_t bad = st + chunk * 5120 + brow + inner;
                uint32_t r0, r1, r2, r3;
                uint32_t bh0[2], bh1[2], bl0[2], bl1[2];
                ldsm4(r0, r1, r2, r3, bad);
                bh0[0] = r0; bh0[1] = r2; bh1[0] = r1; bh1[1] = r3;
                ldsm4(r0, r1, r2, r3, bad + 20480);
                bl0[0] = r0; bl0[1] = r2; bl1[0] = r1; bl1[1] = r3;
                mma16816(sacc[2 * p], th_hi[s], bh0);
                mma16816(sacc[2 * p + 1], th_hi[s], bh1);
                mma16816(sacc[2 * p], th_hi[s], bl0);
                mma16816(sacc[2 * p + 1], th_hi[s], bl1);
                mma16816(sacc[2 * p], th_lo[s], bh0);
                mma16816(sacc[2 * p + 1], th_lo[s], bh1);
            }
        }

        // ---- online softmax (rows r, r+8 per thread) ----
        float tm0 = -1e30f, tm1 = -1e30f;
#pragma unroll
        for (int j = 0; j < 8; j++) {
            tm0 = fmaxf(tm0, fmaxf(sacc[j][0], sacc[j][1]));
            tm1 = fmaxf(tm1, fmaxf(sacc[j][2], sacc[j][3]));
        }
        tm0 = fmaxf(tm0, __shfl_xor_sync(0xffffffffu, tm0, 1));
        tm0 = fmaxf(tm0, __shfl_xor_sync(0xffffffffu, tm0, 2));
        tm1 = fmaxf(tm1, __shfl_xor_sync(0xffffffffu, tm1, 1));
        tm1 = fmaxf(tm1, __shfl_xor_sync(0xffffffffu, tm1, 2));
        float mn0 = fmaxf(rmax0, tm0), mn1 = fmaxf(rmax1, tm1);
        float sc0 = __expf(rmax0 - mn0), sc1 = __expf(rmax1 - mn1);
        float ts0 = 0.f, ts1 = 0.f;
#pragma unroll
        for (int j = 0; j < 8; j++) {
            sacc[j][0] = __expf(sacc[j][0] - mn0);
            sacc[j][1] = __expf(sacc[j][1] - mn0);
            sacc[j][2] = __expf(sacc[j][2] - mn1);
            sacc[j][3] = __expf(sacc[j][3] - mn1);
            ts0 += sacc[j][0] + sacc[j][1];
            ts1 += sacc[j][2] + sacc[j][3];
        }
        ts0 += __shfl_xor_sync(0xffffffffu, ts0, 1);
        ts0 += __shfl_xor_sync(0xffffffffu, ts0, 2);
        ts1 += __shfl_xor_sync(0xffffffffu, ts1, 1);
        ts1 += __shfl_xor_sync(0xffffffffu, ts1, 2);
        rsum0 = rsum0 * sc0 + ts0;
        rsum1 = rsum1 * sc1 + ts1;
        rmax0 = mn0; rmax1 = mn1;
#pragma unroll
        for (int j = 0; j < 16; j++) {
            yacc[j][0] *= sc0; yacc[j][1] *= sc0;
            yacc[j][2] *= sc1; yacc[j][3] *= sc1;
        }

        // ---- pack P into A-frags ----
        uint32_t pf[4][4];
#pragma unroll
        for (int s2 = 0; s2 < 4; s2++) {
            pf[s2][0] = pkh2(sacc[2 * s2][0], sacc[2 * s2][1]);
            pf[s2][1] = pkh2(sacc[2 * s2][2], sacc[2 * s2][3]);
            pf[s2][2] = pkh2(sacc[2 * s2 + 1][0], sacc[2 * s2 + 1][1]);
            pf[s2][3] = pkh2(sacc[2 * s2 + 1][2], sacc[2 * s2 + 1][3]);
        }

        // ---- y += P.g ----
#pragma unroll
        for (int s2 = 0; s2 < 4; s2++) {
            uint32_t chunk = (uint32_t)(s2 >> 1);
            uint32_t inner = (uint32_t)((s2 & 1) * 32 + (lane >> 4) * 16);
#pragma unroll
            for (int pc = 0; pc < 8; pc++) {
                uint32_t brow = (uint32_t)(pc * 16 + (lane & 15)) * 80;
                uint32_t r0, r1, r2, r3;
                ldsm4(r0, r1, r2, r3, st + 40960 + chunk * 10240 + brow + inner);
                uint32_t bb0[2] = {r0, r2};
                uint32_t bb1[2] = {r1, r3};
                mma16816(yacc[2 * pc], pf[s2], bb0);
                mma16816(yacc[2 * pc + 1], pf[s2], bb1);
            }
        }
        __syncthreads();
        if (tid == 0 && mt + 2 < 16) issueM(mt + 2);
    }

    // ---- normalize + write y into yimg (smem-image layout for final GEMM) ----
    float inv0 = 1.f / rsum0, inv1 = 1.f / rsum1;
    int r = lane >> 2, c2 = (lane & 3) * 2;
    char* ybase = g_yimg + (size_t)(b * 32 + nt) * 4 * 10240;
#pragma unroll
    for (int j = 0; j < 16; j++) {
        int col = j * 8 + c2;
        uint32_t v0 = pkh2(yacc[j][0] * inv0, yacc[j][1] * inv0);
        uint32_t v1 = pkh2(yacc[j][2] * inv1, yacc[j][3] * inv1);
        char* p = ybase + (size_t)(col >> 5) * 10240 + lane_off(w * 16 + r, col & 31);
        *(uint32_t*)p = v0;
        *(uint32_t*)(p + 8 * 80) = v1;
    }
}

// ---------------- weight prep -> images + BN constants ----------------
__global__ void wprep_kernel(const float* __restrict__ Wth, const float* __restrict__ Wph,
                             const float* __restrict__ Wg, const float* __restrict__ Ww,
                             const float* __restrict__ gamma, const float* __restrict__ beta,
                             const float* __restrict__ mean, const float* __restrict__ var,
                             const float* __restrict__ bw) {
    int i = blockIdx.x * 256 + threadIdx.x;  // 0..32767
    {
        int row = i >> 8, c = i & 255;
        int ch = c >> 5, cc = c & 31;
        uint32_t off = lane_off(row, cc);
        float a = Wth[i];
        __half h = __float2half_rn(a);
        *(__half*)(g_wthimg + ch * 20480 + off) = h;
        *(__half*)(g_wthimg + ch * 20480 + 10240 + off) = __float2half_rn(a - __half2float(h));
        float p = Wph[i];
        __half hp = __float2half_rn(p);
        *(__half*)(g_wphimg + ch * 20480 + off) = hp;
        *(__half*)(g_wphimg + ch * 20480 + 10240 + off) = __float2half_rn(p - __half2float(hp));
        *(__half*)(g_wgimg + ch * 10240 + off) = __float2half_rn(Wg[i]);
    }
    {
        int row = i >> 7, ci = i & 127;  // Ww [256][128]
        int rt = row >> 7, rr = row & 127;
        int ch = ci >> 5, cc = ci & 31;
        *(__half*)(g_wwimg + (rt * 4 + ch) * 10240 + lane_off(rr, cc)) = __float2half_rn(Ww[i]);
    }
    if (i < CC) {
        float sc = gamma[i] * rsqrtf(var[i] + 1e-5f);
        g_bns[i] = sc;
        g_bnt[i] = beta[i] + (bw[i] - mean[i]) * sc;
    }
}

// ---------------- pool(2x2) + transpose -> pq/pv images ----------------
__global__ void __launch_bounds__(256) pooltrans_kernel(const float* __restrict__ q,
                                                        const float* __restrict__ v) {
    __shared__ float ts[32][33];
    int z = blockIdx.z;
    bool isq = (z < BB);
    const float* src = isq ? q : v;
    int b = z & (BB - 1);
    int m0 = blockIdx.x * 32, c0 = blockIdx.y * 32;
    int tx = threadIdx.x, ty = threadIdx.y;
    const float* sb = src + (size_t)b * CC * NPIX;
    int m = m0 + tx, mi = m >> 5, mj = m & 31;
#pragma unroll
    for (int i = 0; i < 4; i++) {
        int c = c0 + ty + i * 8;
        const float* p = sb + (size_t)c * NPIX + (2 * mi) * WW + 2 * mj;
        ts[ty + i * 8][tx] = 0.25f * (p[0] + p[1] + p[WW] + p[WW + 1]);
    }
    __syncthreads();
    int ch = c0 >> 5;
#pragma unroll
    for (int i = 0; i < 4; i++) {
        float val = ts[tx][ty + i * 8];
        int mm = m0 + ty + i * 8;
        int mtile = mm >> 7, r = mm & 127;
        uint32_t off = lane_off(r, tx);
        __half h = __float2half_rn(val);
        if (isq) {
            char* base = g_pqimg + (size_t)((b * 8 + mtile) * 8 + ch) * 20480;
            *(__half*)(base + off) = h;
            *(__half*)(base + 10240 + off) = __float2half_rn(val - __half2float(h));
        } else {
            *(__half*)(g_pvimg + (size_t)((b * 8 + mtile) * 8 + ch) * 10240 + off) = h;
        }
    }
}

// ---------------- transpose k -> kT image (hi/lo) ----------------
__global__ void __launch_bounds__(256) transk_kernel(const float* __restrict__ k) {
    __shared__ float ts[32][33];
    int b = blockIdx.z;
    int n0 = blockIdx.x * 32, c0 = blockIdx.y * 32;
    int tx = threadIdx.x, ty = threadIdx.y;
    const float* sb = k + (size_t)b * CC * NPIX;
#pragma unroll
    for (int i = 0; i < 4; i++)
        ts[ty + i * 8][tx] = sb[(size_t)(c0 + ty + i * 8) * NPIX + n0 + tx];
    __syncthreads();
    int ch = c0 >> 5;
#pragma unroll
    for (int i = 0; i < 4; i++) {
        float val = ts[tx][ty + i * 8];
        int nn = n0 + ty + i * 8;
        int nt = nn >> 7, r = nn & 127;
        uint32_t off = lane_off(r, tx);
        char* base = g_kimg + (size_t)((b * 32 + nt) * 8 + ch) * 20480;
        __half h = __float2half_rn(val);
        *(__half*)(base + off) = h;
        *(__half*)(base + 10240 + off) = __float2half_rn(val - __half2float(h));
    }
}

// ---------------- launch ----------------
extern "C" void kernel_launch(void* const* d_in, const int* in_sizes, int n_in,
                              void* d_out, int out_size) {
    (void)in_sizes; (void)n_in; (void)out_size;
    const float* q     = (const float*)d_in[0];
    const float* k     = (const float*)d_in[1];
    const float* v     = (const float*)d_in[2];
    const float* Wg    = (const float*)d_in[3];
    const float* bg    = (const float*)d_in[4];
    const float* Wth   = (const float*)d_in[5];
    const float* bth   = (const float*)d_in[6];
    const float* Wph   = (const float*)d_in[7];
    const float* bph   = (const float*)d_in[8];
    const float* Ww    = (const float*)d_in[9];
    const float* bw    = (const float*)d_in[10];
    const float* gamma = (const float*)d_in[11];
    const float* beta  = (const float*)d_in[12];
    const float* mean  = (const float*)d_in[13];
    const float* var   = (const float*)d_in[14];
    float* out = (float*)d_out;

    char *kimg, *wthimg, *wphimg, *wgimg, *wwimg, *pqimg, *pvimg, *pgimg, *yimg;
    cudaGetSymbolAddress((void**)&kimg, g_kimg);
    cudaGetSymbolAddress((void**)&wthimg, g_wthimg);
    cudaGetSymbolAddress((void**)&wphimg, g_wphimg);
    cudaGetSymbolAddress((void**)&wgimg, g_wgimg);
    cudaGetSymbolAddress((void**)&wwimg, g_wwimg);
    cudaGetSymbolAddress((void**)&pqimg, g_pqimg);
    cudaGetSymbolAddress((void**)&pvimg, g_pvimg);
    cudaGetSymbolAddress((void**)&pgimg, g_pgimg);
    cudaGetSymbolAddress((void**)&yimg, g_yimg);
    (void)kimg; (void)wthimg;

    const int SMS = 81920;   // split: 2 x 40960
    const int SMN = 40960;   // plain: 2 x 20480
    const int SMF = 122880;  // flash: 2 x 61440
    cudaFuncSetAttribute(hgemmB<8, true, 5>, cudaFuncAttributeMaxDynamicSharedMemorySize, SMS);
    cudaFuncSetAttribute(hgemmB<8, false, 6>, cudaFuncAttributeMaxDynamicSharedMemorySize, SMN);
    cudaFuncSetAttribute(hgemmB<4, false, 4>, cudaFuncAttributeMaxDynamicSharedMemorySize, SMN);
    cudaFuncSetAttribute(flash_kernel, cudaFuncAttributeMaxDynamicSharedMemorySize, SMF);

    // 1) prep -> images
    wprep_kernel<<<CHI * CC / 256, 256>>>(Wth, Wph, Wg, Ww, gamma, beta, mean, var, bw);
    pooltrans_kernel<<<dim3(MPOOL / 32, CC / 32, 2 * BB), dim3(32, 8)>>>(q, v);
    transk_kernel<<<dim3(NPIX / 32, CC / 32, BB), dim3(32, 8)>>>(k);

    // 2) phi = pq.Wph^T (+bph) -> pgimg  [A idx = z*8+by; B idx = 0]
    hgemmB<8, true, 5><<<dim3(1, MPOOL / 128, BB), 256, SMS>>>(
        pqimg, wphimg, 8, 1, 0, 0, 0, 0, bph, pgimg, nullptr, nullptr);
    // 3) g = Wg.pv^T (+bg row) -> pgimg  [A idx = 0; B idx = z*8+bx]
    hgemmB<8, false, 6><<<dim3(MPOOL / 128, 1, BB), 256, SMN>>>(
        wgimg, pvimg, 0, 0, 0, 8, 0, 1, bg, pgimg, nullptr, nullptr);
    // 4) fused: theta prologue + flash attention -> yimg
    flash_kernel<<<dim3(NPIX / 128, BB), 256, SMF>>>(bth);
    // 5) out = BN(Ww.y^T) + v  [A idx = by; B idx = z*32+bx]
    hgemmB<4, false, 4><<<dim3(NPIX / 128, CC / 128, BB), 256, SMN>>>(
        wwimg, yimg, 0, 1, 0, 32, 0, 1, nullptr, nullptr, out, v);
}

// round 8
// speedup vs baseline: 3.3777x; 1.0449x over previous
#include <cuda_runtime.h>
#include <cuda_fp16.h>
#include <cstdint>
#include <cstddef>

// Problem dims
#define BB   8
#define CC   256
#define CHI  128
#define HH   64
#define WW   64
#define NPIX 4096   // H*W
#define MPOOL 1024  // (H/2)*(W/2)

// ---------------- gmem "smem-image" buffers ----------------
// lane_off(r, c<32) = r*80 + (c>>3)*16 + (c&7)*2
__device__ __align__(128) char g_kimg[(size_t)8 * 32 * 8 * 20480];
__device__ __align__(128) char g_wthimg[8 * 20480];
__device__ __align__(128) char g_wphimg[8 * 20480];
__device__ __align__(128) char g_wgimg[8 * 10240];
__device__ __align__(128) char g_wwimg[8 * 10240];
__device__ __align__(128) char g_pqimg[(size_t)8 * 8 * 8 * 20480];
__device__ __align__(128) char g_pvimg[(size_t)8 * 8 * 8 * 10240];
__device__ __align__(128) char g_pgimg[(size_t)8 * 16 * 61440];
__device__ __align__(128) char g_yimg[(size_t)8 * 32 * 4 * 10240];
__device__ float g_bns[CC];
__device__ float g_bnt[CC];

// ---------------- PTX helpers ----------------
__device__ __forceinline__ uint32_t smem_u32(const void* p) {
    uint32_t a;
    asm("{ .reg .u64 t; cvta.to.shared.u64 t, %1; cvt.u32.u64 %0, t; }" : "=r"(a) : "l"(p));
    return a;
}
__device__ __forceinline__ void cpbulk(uint32_t dst, const void* src, uint32_t bytes,
                                       uint32_t mbar) {
    asm volatile(
        "cp.async.bulk.shared::cluster.global.mbarrier::complete_tx::bytes [%0], [%1], %2, [%3];"
        :: "r"(dst), "l"(src), "r"(bytes), "r"(mbar) : "memory");
}
#define MBAR_INIT(mb, n) \
    asm volatile("mbarrier.init.shared.b64 [%0], %1;" :: "r"(mb), "r"((uint32_t)(n)) : "memory")
#define MBAR_EXPECT(mb, n) \
    asm volatile("mbarrier.arrive.expect_tx.shared.b64 _, [%0], %1;" :: "r"(mb), "r"((uint32_t)(n)) : "memory")

__device__ __forceinline__ void mbar_wait(uint32_t mb, uint32_t parity) {
    uint32_t done;
    asm volatile(
        "{\n\t.reg .pred p;\n\t"
        "mbarrier.try_wait.parity.acquire.cta.shared::cta.b64 p, [%1], %2;\n\t"
        "selp.b32 %0, 1, 0, p;\n\t}"
        : "=r"(done) : "r"(mb), "r"(parity) : "memory");
    if (!done) {
        asm volatile(
            "{\n\t.reg .pred P1;\n\t"
            "W0_%=:\n\t"
            "mbarrier.try_wait.parity.acquire.cta.shared::cta.b64 P1, [%0], %1, 0x989680;\n\t"
            "@P1 bra.uni W1_%=;\n\t"
            "bra.uni W0_%=;\n\t"
            "W1_%=:\n\t}"
            :: "r"(mb), "r"(parity) : "memory");
    }
}
__device__ __forceinline__ void ldsm4(uint32_t& r0, uint32_t& r1, uint32_t& r2, uint32_t& r3,
                                      uint32_t a) {
    asm volatile("ldmatrix.sync.aligned.m8n8.x4.shared.b16 {%0,%1,%2,%3}, [%4];"
                 : "=r"(r0), "=r"(r1), "=r"(r2), "=r"(r3) : "r"(a));
}
__device__ __forceinline__ void mma16816(float* c, const uint32_t* a, const uint32_t* b) {
    asm volatile(
        "mma.sync.aligned.m16n8k16.row.col.f32.f16.f16.f32 "
        "{%0,%1,%2,%3}, {%4,%5,%6,%7}, {%8,%9}, {%0,%1,%2,%3};"
        : "+f"(c[0]), "+f"(c[1]), "+f"(c[2]), "+f"(c[3])
        : "r"(a[0]), "r"(a[1]), "r"(a[2]), "r"(a[3]), "r"(b[0]), "r"(b[1]));
}
__device__ __forceinline__ uint32_t pkh2(float a, float b) {
    __half2 h = __floats2half2_rn(a, b);
    return *(uint32_t*)&h;
}
__device__ __forceinline__ uint32_t lane_off(int r, int c) {
    return (uint32_t)(r * 80 + (c >> 3) * 16 + (c & 7) * 2);
}

// ---------------- 3-stage bulk-fed GEMM body ----------------
// EPI 5: phi -> pgimg (col bias, split hi/lo) | 6: g -> pgimg (row bias)
// EPI 4: final -> fp32 out with BN(row)+resid
template <int NCH, bool SPLIT, int EPI>
__device__ __forceinline__ void gemm_body(
    const char* __restrict__ Ab, const char* __restrict__ Bb,
    char* smraw, uint32_t mb0, int z, int by, int bx,
    const float* __restrict__ bias, char* __restrict__ outImg,
    float* __restrict__ outF, const float* __restrict__ resid, int tid) {
    constexpr uint32_t REG = SPLIT ? 20480 : 10240;
    constexpr uint32_t STAGE = SPLIT ? 40960 : 20480;
    uint32_t sbase = smem_u32(smraw);
    int lane = tid & 31, w = tid >> 5;
    int wm = w >> 2, wn = w & 3;

    if (tid == 0) { MBAR_INIT(mb0, 1); MBAR_INIT(mb0 + 8, 1); MBAR_INIT(mb0 + 16, 1); }
    __syncthreads();

    auto issue = [&](int ch) {
        uint32_t st = sbase + (uint32_t)(ch % 3) * STAGE;
        uint32_t mb = mb0 + (uint32_t)(ch % 3) * 8;
        MBAR_EXPECT(mb, SPLIT ? 40960u : 20480u);
        if (SPLIT) {
            cpbulk(st, Ab + (size_t)ch * REG, 10240, mb);
            cpbulk(st + 20480, Ab + (size_t)ch * REG + 10240, 10240, mb);
            cpbulk(st + 10240, Bb + (size_t)ch * REG, 10240, mb);
            cpbulk(st + 30720, Bb + (size_t)ch * REG + 10240, 10240, mb);
        } else {
            cpbulk(st, Ab + (size_t)ch * REG, 10240, mb);
            cpbulk(st + 10240, Bb + (size_t)ch * REG, 10240, mb);
        }
    };
    if (tid == 0) { issue(0); issue(1); issue(2); }

    float acc[4][4][4];
#pragma unroll
    for (int i = 0; i < 4; i++)
#pragma unroll
        for (int j = 0; j < 4; j++)
#pragma unroll
            for (int e = 0; e < 4; e++) acc[i][j][e] = 0.f;

    for (int ch = 0; ch < NCH; ch++) {
        mbar_wait(mb0 + (uint32_t)(ch % 3) * 8, (uint32_t)((ch / 3) & 1));
        uint32_t sa = sbase + (uint32_t)(ch % 3) * STAGE;
        uint32_t sb = sa + 10240;
#pragma unroll
        for (int k16 = 0; k16 < 2; k16++) {
            uint32_t a[4][4], b[4][2];
            uint32_t coff = (uint32_t)(k16 * 32 + (lane >> 4) * 16);
#pragma unroll
            for (int mi = 0; mi < 4; mi++) {
                uint32_t ad = sa + (uint32_t)(wm * 64 + mi * 16 + (lane & 15)) * 80 + coff;
                ldsm4(a[mi][0], a[mi][1], a[mi][2], a[mi][3], ad);
            }
#pragma unroll
            for (int nh = 0; nh < 2; nh++) {
                uint32_t bd = sb + (uint32_t)(wn * 32 + nh * 16 + (lane & 15)) * 80 + coff;
                uint32_t r0, r1, r2, r3;
                ldsm4(r0, r1, r2, r3, bd);
                b[nh * 2 + 0][0] = r0; b[nh * 2 + 0][1] = r2;
                b[nh * 2 + 1][0] = r1; b[nh * 2 + 1][1] = r3;
            }
#pragma unroll
            for (int mi = 0; mi < 4; mi++)
#pragma unroll
                for (int ni = 0; ni < 4; ni++) mma16816(acc[mi][ni], a[mi], b[ni]);
            if (SPLIT) {
                uint32_t al[4][4], bl[4][2];
#pragma unroll
                for (int mi = 0; mi < 4; mi++) {
                    uint32_t ad = sa + 20480 + (uint32_t)(wm * 64 + mi * 16 + (lane & 15)) * 80 + coff;
                    ldsm4(al[mi][0], al[mi][1], al[mi][2], al[mi][3], ad);
                }
#pragma unroll
                for (int nh = 0; nh < 2; nh++) {
                    uint32_t bd = sa + 30720 + (uint32_t)(wn * 32 + nh * 16 + (lane & 15)) * 80 + coff;
                    uint32_t r0, r1, r2, r3;
                    ldsm4(r0, r1, r2, r3, bd);
                    bl[nh * 2 + 0][0] = r0; bl[nh * 2 + 0][1] = r2;
                    bl[nh * 2 + 1][0] = r1; bl[nh * 2 + 1][1] = r3;
                }
#pragma unroll
                for (int mi = 0; mi < 4; mi++)
#pragma unroll
                    for (int ni = 0; ni < 4; ni++) {
                        mma16816(acc[mi][ni], a[mi], bl[ni]);
                        mma16816(acc[mi][ni], al[mi], b[ni]);
                    }
            }
        }
        __syncthreads();
        if (tid == 0 && ch + 3 < NCH) issue(ch + 3);
    }

    int r = lane >> 2, cp2 = (lane & 3) * 2;
    int row0 = by * 128 + wm * 64;
    int col0 = bx * 128 + wn * 32;
#pragma unroll
    for (int mi = 0; mi < 4; mi++) {
#pragma unroll
        for (int h = 0; h < 2; h++) {
            int row = row0 + mi * 16 + h * 8 + r;
            float s = 1.f, t = 0.f;
            if (EPI == 6) t = bias[row];
            if (EPI == 4) { s = g_bns[row]; t = g_bnt[row]; }
#pragma unroll
            for (int ni = 0; ni < 4; ni++) {
                int col = col0 + ni * 8 + cp2;
                float v0 = acc[mi][ni][h * 2 + 0];
                float v1 = acc[mi][ni][h * 2 + 1];
                if (EPI == 5) {
                    v0 += bias[col]; v1 += bias[col + 1];
                    __half h0 = __float2half_rn(v0), h1 = __float2half_rn(v1);
                    uint32_t hi = ((uint32_t)*(uint16_t*)&h1 << 16) | *(uint16_t*)&h0;
                    uint32_t lo = pkh2(v0 - __half2float(h0), v1 - __half2float(h1));
                    char* base = outImg + (size_t)(z * 16 + (row >> 6)) * 61440;
                    uint32_t off = (uint32_t)(col >> 5) * 5120 + lane_off(row & 63, col & 31);
                    *(uint32_t*)(base + off) = hi;
                    *(uint32_t*)(base + off + 20480) = lo;
                } else if (EPI == 6) {
                    uint32_t hv = pkh2(v0 + t, v1 + t);
                    char* base = outImg + (size_t)(z * 16 + (col >> 6)) * 61440 + 40960;
                    uint32_t off = (uint32_t)((col >> 5) & 1) * 10240 + lane_off(row, col & 31);
                    *(uint32_t*)(base + off) = hv;
                } else {
                    const float* rp = resid + (size_t)z * CC * NPIX + (size_t)row * NPIX + col;
                    float* op = outF + (size_t)z * CC * NPIX + (size_t)row * NPIX + col;
                    op[0] = v0 * s + t + rp[0];
                    op[1] = v1 * s + t + rp[1];
                }
            }
        }
    }
}

// ---------------- mid kernel: phi (blocks 0-63) + g (blocks 64-127) ----------------
__global__ void __launch_bounds__(256, 1) mid_kernel(const float* __restrict__ bph,
                                                     const float* __restrict__ bg) {
    extern __shared__ char sm[];
    __shared__ __align__(8) uint64_t s_mbar[3];
    int tid = threadIdx.x;
    uint32_t mb0 = smem_u32(&s_mbar[0]);
    if (blockIdx.x < 64) {
        int z = blockIdx.x >> 3, by = blockIdx.x & 7;
        const char* Ab = g_pqimg + (size_t)(z * 8 + by) * (8 * 20480);
        gemm_body<8, true, 5>(Ab, g_wphimg, sm, mb0, z, by, 0, bph, g_pgimg, nullptr, nullptr, tid);
    } else {
        int i = blockIdx.x - 64;
        int z = i >> 3, bx = i & 7;
        const char* Bb = g_pvimg + (size_t)(z * 8 + bx) * (8 * 10240);
        gemm_body<8, false, 6>(g_wgimg, Bb, sm, mb0, z, 0, bx, bg, g_pgimg, nullptr, nullptr, tid);
    }
}

// ---------------- final kernel ----------------
__global__ void __launch_bounds__(256, 1) final_kernel(const float* __restrict__ v,
                                                       float* __restrict__ out) {
    extern __shared__ char sm[];
    __shared__ __align__(8) uint64_t s_mbar[3];
    int tid = threadIdx.x;
    uint32_t mb0 = smem_u32(&s_mbar[0]);
    int z = blockIdx.z, by = blockIdx.y, bx = blockIdx.x;
    const char* Ab = g_wwimg + (size_t)by * (4 * 10240);
    const char* Bb = g_yimg + (size_t)(z * 32 + bx) * (4 * 10240);
    gemm_body<4, false, 4>(Ab, Bb, sm, mb0, z, by, bx, nullptr, nullptr, out, v, tid);
}

// ---------------- fused flash: theta prologue + S-softmax-y, 3-stage bulk ----------------
__global__ void __launch_bounds__(256, 1) flash_kernel(const float* __restrict__ bth) {
    extern __shared__ char sm[];
    __shared__ __align__(8) uint64_t s_mbar[3];
    uint32_t sbase = smem_u32(sm);
    uint32_t mb0 = smem_u32(&s_mbar[0]);
    const uint32_t STGSZ = 61440;

    int tid = threadIdx.x, lane = tid & 31, w = tid >> 5;
    int b = blockIdx.y;
    int nt = blockIdx.x;
    const char* kimgT = g_kimg + (size_t)(b * 32 + nt) * 8 * 20480;
    const char* pgB = g_pgimg + (size_t)b * 16 * 61440;

    if (tid == 0) { MBAR_INIT(mb0, 1); MBAR_INIT(mb0 + 8, 1); MBAR_INIT(mb0 + 16, 1); }
    __syncthreads();

    // unified chunk counter t: 0..7 prologue (k+Wth), 8..23 main (phi+g)
    auto issue = [&](int t) {
        uint32_t st = sbase + (uint32_t)(t % 3) * STGSZ;
        uint32_t mb = mb0 + (uint32_t)(t % 3) * 8;
        if (t < 8) {
            MBAR_EXPECT(mb, 40960u);
            cpbulk(st, kimgT + (size_t)t * 20480, 20480, mb);
            cpbulk(st + 20480, g_wthimg + (size_t)t * 20480, 20480, mb);
        } else {
            MBAR_EXPECT(mb, 61440u);
            cpbulk(st, pgB + (size_t)(t - 8) * 61440, 61440, mb);
        }
    };
    if (tid == 0) { issue(0); issue(1); issue(2); }

    // ======== PROLOGUE: theta = kT.Wth^T (3-pass split) ========
    float acc[16][4];
#pragma unroll
    for (int j = 0; j < 16; j++)
#pragma unroll
        for (int e = 0; e < 4; e++) acc[j][e] = 0.f;

    for (int ch = 0; ch < 8; ch++) {
        mbar_wait(mb0 + (uint32_t)(ch % 3) * 8, (uint32_t)((ch / 3) & 1));
        uint32_t st = sbase + (uint32_t)(ch % 3) * STGSZ;
#pragma unroll
        for (int k16 = 0; k16 < 2; k16++) {
            uint32_t coff = (uint32_t)(k16 * 32 + (lane >> 4) * 16);
            uint32_t arow = (uint32_t)(w * 16 + (lane & 15)) * 80;
            uint32_t ah[4], al[4];
            ldsm4(ah[0], ah[1], ah[2], ah[3], st + arow + coff);
            ldsm4(al[0], al[1], al[2], al[3], st + 10240 + arow + coff);
#pragma unroll
            for (int nh = 0; nh < 8; nh++) {
                uint32_t brow = (uint32_t)(nh * 16 + (lane & 15)) * 80;
                uint32_t r0, r1, r2, r3;
                uint32_t bh0[2], bh1[2], bl0[2], bl1[2];
                ldsm4(r0, r1, r2, r3, st + 20480 + brow + coff);
                bh0[0] = r0; bh0[1] = r2; bh1[0] = r1; bh1[1] = r3;
                ldsm4(r0, r1, r2, r3, st + 30720 + brow + coff);
                bl0[0] = r0; bl0[1] = r2; bl1[0] = r1; bl1[1] = r3;
                mma16816(acc[2 * nh], ah, bh0);
                mma16816(acc[2 * nh + 1], ah, bh1);
                mma16816(acc[2 * nh], ah, bl0);
                mma16816(acc[2 * nh + 1], ah, bl1);
                mma16816(acc[2 * nh], al, bh0);
                mma16816(acc[2 * nh + 1], al, bh1);
            }
        }
        __syncthreads();
        if (tid == 0) issue(ch + 3);
    }

    // bias + hi/lo split -> A-fragments
    uint32_t th_hi[8][4], th_lo[8][4];
    {
        int t2 = (lane & 3) * 2;
#pragma unroll
        for (int s = 0; s < 8; s++) {
#pragma unroll
            for (int hf = 0; hf < 2; hf++) {
                int nb = 2 * s + hf;
                float b0 = bth[8 * nb + t2], b1 = bth[8 * nb + t2 + 1];
                float x0 = acc[nb][0] + b0, x1 = acc[nb][1] + b1;
                float x2 = acc[nb][2] + b0, x3 = acc[nb][3] + b1;
                __half hx0 = __float2half_rn(x0), hx1 = __float2half_rn(x1);
                __half hx2 = __float2half_rn(x2), hx3 = __float2half_rn(x3);
                th_hi[s][2 * hf + 0] = ((uint32_t)*(uint16_t*)&hx1 << 16) | *(uint16_t*)&hx0;
                th_hi[s][2 * hf + 1] = ((uint32_t)*(uint16_t*)&hx3 << 16) | *(uint16_t*)&hx2;
                th_lo[s][2 * hf + 0] = pkh2(x0 - __half2float(hx0), x1 - __half2float(hx1));
                th_lo[s][2 * hf + 1] = pkh2(x2 - __half2float(hx2), x3 - __half2float(hx3));
            }
        }
    }

    // ======== MAIN LOOP ========
    float yacc[16][4];
#pragma unroll
    for (int j = 0; j < 16; j++)
#pragma unroll
        for (int e = 0; e < 4; e++) yacc[j][e] = 0.f;
    float rmax0 = -1e30f, rmax1 = -1e30f, rsum0 = 0.f, rsum1 = 0.f;

    for (int mt = 0; mt < 16; mt++) {
        int t = 8 + mt;
        mbar_wait(mb0 + (uint32_t)(t % 3) * 8, (uint32_t)((t / 3) & 1));
        uint32_t st = sbase + (uint32_t)(t % 3) * STGSZ;

        float sacc[8][4];
#pragma unroll
        for (int j = 0; j < 8; j++)
#pragma unroll
            for (int e = 0; e < 4; e++) sacc[j][e] = 0.f;

#pragma unroll
        for (int s = 0; s < 8; s++) {
            uint32_t chunk = (uint32_t)(s >> 1);
            uint32_t inner = (uint32_t)((s & 1) * 32 + (lane >> 4) * 16);
#pragma unroll
            for (int p = 0; p < 4; p++) {
                uint32_t brow = (uint32_t)(p * 16 + (lane & 15)) * 80;
                uint32_t bad = st + chunk * 5120 + brow + inner;
                uint32_t r0, r1, r2, r3;
                uint32_t bh0[2], bh1[2], bl0[2], bl1[2];
                ldsm4(r0, r1, r2, r3, bad);
                bh0[0] = r0; bh0[1] = r2; bh1[0] = r1; bh1[1] = r3;
                ldsm4(r0, r1, r2, r3, bad + 20480);
                bl0[0] = r0; bl0[1] = r2; bl1[0] = r1; bl1[1] = r3;
                mma16816(sacc[2 * p], th_hi[s], bh0);
                mma16816(sacc[2 * p + 1], th_hi[s], bh1);
                mma16816(sacc[2 * p], th_hi[s], bl0);
                mma16816(sacc[2 * p + 1], th_hi[s], bl1);
                mma16816(sacc[2 * p], th_lo[s], bh0);
                mma16816(sacc[2 * p + 1], th_lo[s], bh1);
            }
        }

        float tm0 = -1e30f, tm1 = -1e30f;
#pragma unroll
        for (int j = 0; j < 8; j++) {
            tm0 = fmaxf(tm0, fmaxf(sacc[j][0], sacc[j][1]));
            tm1 = fmaxf(tm1, fmaxf(sacc[j][2], sacc[j][3]));
        }
        tm0 = fmaxf(tm0, __shfl_xor_sync(0xffffffffu, tm0, 1));
        tm0 = fmaxf(tm0, __shfl_xor_sync(0xffffffffu, tm0, 2));
        tm1 = fmaxf(tm1, __shfl_xor_sync(0xffffffffu, tm1, 1));
        tm1 = fmaxf(tm1, __shfl_xor_sync(0xffffffffu, tm1, 2));
        float mn0 = fmaxf(rmax0, tm0), mn1 = fmaxf(rmax1, tm1);
        float sc0 = __expf(rmax0 - mn0), sc1 = __expf(rmax1 - mn1);
        float ts0 = 0.f, ts1 = 0.f;
#pragma unroll
        for (int j = 0; j < 8; j++) {
            sacc[j][0] = __expf(sacc[j][0] - mn0);
            sacc[j][1] = __expf(sacc[j][1] - mn0);
            sacc[j][2] = __expf(sacc[j][2] - mn1);
            sacc[j][3] = __expf(sacc[j][3] - mn1);
            ts0 += sacc[j][0] + sacc[j][1];
            ts1 += sacc[j][2] + sacc[j][3];
        }
        ts0 += __shfl_xor_sync(0xffffffffu, ts0, 1);
        ts0 += __shfl_xor_sync(0xffffffffu, ts0, 2);
        ts1 += __shfl_xor_sync(0xffffffffu, ts1, 1);
        ts1 += __shfl_xor_sync(0xffffffffu, ts1, 2);
        rsum0 = rsum0 * sc0 + ts0;
        rsum1 = rsum1 * sc1 + ts1;
        rmax0 = mn0; rmax1 = mn1;
#pragma unroll
        for (int j = 0; j < 16; j++) {
            yacc[j][0] *= sc0; yacc[j][1] *= sc0;
            yacc[j][2] *= sc1; yacc[j][3] *= sc1;
        }

        uint32_t pf[4][4];
#pragma unroll
        for (int s2 = 0; s2 < 4; s2++) {
            pf[s2][0] = pkh2(sacc[2 * s2][0], sacc[2 * s2][1]);
            pf[s2][1] = pkh2(sacc[2 * s2][2], sacc[2 * s2][3]);
            pf[s2][2] = pkh2(sacc[2 * s2 + 1][0], sacc[2 * s2 + 1][1]);
            pf[s2][3] = pkh2(sacc[2 * s2 + 1][2], sacc[2 * s2 + 1][3]);
        }

#pragma unroll
        for (int s2 = 0; s2 < 4; s2++) {
            uint32_t chunk = (uint32_t)(s2 >> 1);
            uint32_t inner = (uint32_t)((s2 & 1) * 32 + (lane >> 4) * 16);
#pragma unroll
            for (int pc = 0; pc < 8; pc++) {
                uint32_t brow = (uint32_t)(pc * 16 + (lane & 15)) * 80;
                uint32_t r0, r1, r2, r3;
                ldsm4(r0, r1, r2, r3, st + 40960 + chunk * 10240 + brow + inner);
                uint32_t bb0[2] = {r0, r2};
                uint32_t bb1[2] = {r1, r3};
                mma16816(yacc[2 * pc], pf[s2], bb0);
                mma16816(yacc[2 * pc + 1], pf[s2], bb1);
            }
        }
        __syncthreads();
        if (tid == 0 && t + 3 < 24) issue(t + 3);
    }

    // ---- normalize + write y into yimg ----
    float inv0 = 1.f / rsum0, inv1 = 1.f / rsum1;
    int r = lane >> 2, c2 = (lane & 3) * 2;
    char* ybase = g_yimg + (size_t)(b * 32 + nt) * 4 * 10240;
#pragma unroll
    for (int j = 0; j < 16; j++) {
        int col = j * 8 + c2;
        uint32_t v0 = pkh2(yacc[j][0] * inv0, yacc[j][1] * inv0);
        uint32_t v1 = pkh2(yacc[j][2] * inv1, yacc[j][3] * inv1);
        char* p = ybase + (size_t)(col >> 5) * 10240 + lane_off(w * 16 + r, col & 31);
        *(uint32_t*)p = v0;
        *(uint32_t*)(p + 8 * 80) = v1;
    }
}

// ---------------- merged prep: pooltrans (0..4095) + transk (4096..12287) + wprep ----------------
__global__ void __launch_bounds__(256) prep_kernel(
    const float* __restrict__ q, const float* __restrict__ v, const float* __restrict__ k,
    const float* __restrict__ Wth, const float* __restrict__ Wph,
    const float* __restrict__ Wg, const float* __restrict__ Ww,
    const float* __restrict__ gamma, const float* __restrict__ beta,
    const float* __restrict__ mean, const float* __restrict__ var,
    const float* __restrict__ bw) {
    __shared__ float ts[32][33];
    int bid = blockIdx.x;
    int tid = threadIdx.x;
    int tx = tid & 31, ty = tid >> 5;

    if (bid < 4096) {
        // pool(2x2) + transpose q/v -> pq/pv images
        int z = bid >> 8, rem = bid & 255;
        int m0 = (rem & 31) * 32, c0 = (rem >> 5) * 32;
        bool isq = (z < BB);
        const float* src = isq ? q : v;
        int b = z & (BB - 1);
        const float* sb = src + (size_t)b * CC * NPIX;
        int m = m0 + tx, mi = m >> 5, mj = m & 31;
#pragma unroll
        for (int i = 0; i < 4; i++) {
            int c = c0 + ty + i * 8;
            const float* p = sb + (size_t)c * NPIX + (2 * mi) * WW + 2 * mj;
            ts[ty + i * 8][tx] = 0.25f * (p[0] + p[1] + p[WW] + p[WW + 1]);
        }
        __syncthreads();
        int ch = c0 >> 5;
#pragma unroll
        for (int i = 0; i < 4; i++) {
            float val = ts[tx][ty + i * 8];
            int mm = m0 + ty + i * 8;
            int mtile = mm >> 7, r = mm & 127;
            uint32_t off = lane_off(r, tx);
            __half h = __float2half_rn(val);
            if (isq) {
                char* base = g_pqimg + (size_t)((b * 8 + mtile) * 8 + ch) * 20480;
                *(__half*)(base + off) = h;
                *(__half*)(base + 10240 + off) = __float2half_rn(val - __half2float(h));
            } else {
                *(__half*)(g_pvimg + (size_t)((b * 8 + mtile) * 8 + ch) * 10240 + off) = h;
            }
        }
    } else if (bid < 12288) {
        // transpose k -> kT image (hi/lo)
        int i = bid - 4096;
        int b = i >> 10;
        int n0 = (i & 127) * 32, c0 = ((i >> 7) & 7) * 32;
        const float* sb = k + (size_t)b * CC * NPIX;
#pragma unroll
        for (int j = 0; j < 4; j++)
            ts[ty + j * 8][tx] = sb[(size_t)(c0 + ty + j * 8) * NPIX + n0 + tx];
        __syncthreads();
        int ch = c0 >> 5;
#pragma unroll
        for (int j = 0; j < 4; j++) {
            float val = ts[tx][ty + j * 8];
            int nn = n0 + ty + j * 8;
            int nt = nn >> 7, r = nn & 127;
            uint32_t off = lane_off(r, tx);
            char* base = g_kimg + (size_t)((b * 32 + nt) * 8 + ch) * 20480;
            __half h = __float2half_rn(val);
            *(__half*)(base + off) = h;
            *(__half*)(base + 10240 + off) = __float2half_rn(val - __half2float(h));
        }
    } else {
        // weight prep + BN constants
        int i = (bid - 12288) * 256 + tid;
        {
            int row = i >> 8, c = i & 255;
            int ch = c >> 5, cc = c & 31;
            uint32_t off = lane_off(row, cc);
            float a = Wth[i];
            __half h = __float2half_rn(a);
            *(__half*)(g_wthimg + ch * 20480 + off) = h;
            *(__half*)(g_wthimg + ch * 20480 + 10240 + off) = __float2half_rn(a - __half2float(h));
            float p = Wph[i];
            __half hp = __float2half_rn(p);
            *(__half*)(g_wphimg + ch * 20480 + off) = hp;
            *(__half*)(g_wphimg + ch * 20480 + 10240 + off) = __float2half_rn(p - __half2float(hp));
            *(__half*)(g_wgimg + ch * 10240 + off) = __float2half_rn(Wg[i]);
        }
        {
            int row = i >> 7, ci = i & 127;
            int rt = row >> 7, rr = row & 127;
            int ch = ci >> 5, cc = ci & 31;
            *(__half*)(g_wwimg + (rt * 4 + ch) * 10240 + lane_off(rr, cc)) = __float2half_rn(Ww[i]);
        }
        if (i < CC) {
            float sc = gamma[i] * rsqrtf(var[i] + 1e-5f);
            g_bns[i] = sc;
            g_bnt[i] = beta[i] + (bw[i] - mean[i]) * sc;
        }
    }
}

// ---------------- launch ----------------
extern "C" void kernel_launch(void* const* d_in, const int* in_sizes, int n_in,
                              void* d_out, int out_size) {
    (void)in_sizes; (void)n_in; (void)out_size;
    const float* q     = (const float*)d_in[0];
    const float* k     = (const float*)d_in[1];
    const float* v     = (const float*)d_in[2];
    const float* Wg    = (const float*)d_in[3];
    const float* bg    = (const float*)d_in[4];
    const float* Wth   = (const float*)d_in[5];
    const float* bth   = (const float*)d_in[6];
    const float* Wph   = (const float*)d_in[7];
    const float* bph   = (const float*)d_in[8];
    const float* Ww    = (const float*)d_in[9];
    const float* bw    = (const float*)d_in[10];
    const float* gamma = (const float*)d_in[11];
    const float* beta  = (const float*)d_in[12];
    const float* mean  = (const float*)d_in[13];
    const float* var   = (const float*)d_in[14];
    float* out = (float*)d_out;

    const int SMM = 122880;  // mid: 3 x 40960
    const int SMF = 184320;  // flash: 3 x 61440
    const int SML = 61440;   // final: 3 x 20480
    cudaFuncSetAttribute(mid_kernel, cudaFuncAttributeMaxDynamicSharedMemorySize, SMM);
    cudaFuncSetAttribute(flash_kernel, cudaFuncAttributeMaxDynamicSharedMemorySize, SMF);
    cudaFuncSetAttribute(final_kernel, cudaFuncAttributeMaxDynamicSharedMemorySize, SML);

    // 1) merged prep -> images (pool+transpose+weights in one launch)
    prep_kernel<<<12416, 256>>>(q, v, k, Wth, Wph, Wg, Ww, gamma, beta, mean, var, bw);
    // 2) phi + g projections in one launch
    mid_kernel<<<128, 256, SMM>>>(bph, bg);
    // 3) fused: theta prologue + flash attention -> yimg
    flash_kernel<<<dim3(NPIX / 128, BB), 256, SMF>>>(bth);
    // 4) out = BN(Ww.y^T) + v
    final_kernel<<<dim3(NPIX / 128, CC / 128, BB), 256, SML>>>(v, out);
}

// round 9
// speedup vs baseline: 3.6210x; 1.0720x over previous
#include <cuda_runtime.h>
#include <cuda_fp16.h>
#include <cstdint>
#include <cstddef>

// Problem dims
#define BB   8
#define CC   256
#define CHI  128
#define HH   64
#define WW   64
#define NPIX 4096   // H*W
#define MPOOL 1024  // (H/2)*(W/2)

// ---------------- gmem "smem-image" buffers ----------------
// lane_off(r, c<32) = r*80 + (c>>3)*16 + (c&7)*2
__device__ __align__(128) char g_kimg[(size_t)8 * 32 * 8 * 20480];
__device__ __align__(128) char g_wthimg[8 * 20480];
__device__ __align__(128) char g_wphimg[8 * 20480];
__device__ __align__(128) char g_wgimg[8 * 10240];
__device__ __align__(128) char g_wwimg[8 * 10240];
__device__ __align__(128) char g_pqimg[(size_t)8 * 8 * 8 * 20480];
__device__ __align__(128) char g_pvimg[(size_t)8 * 8 * 8 * 10240];
__device__ __align__(128) char g_pgimg[(size_t)8 * 16 * 61440];
__device__ float g_bns[CC];
__device__ float g_bnt[CC];

// ---------------- PTX helpers ----------------
__device__ __forceinline__ uint32_t smem_u32(const void* p) {
    uint32_t a;
    asm("{ .reg .u64 t; cvta.to.shared.u64 t, %1; cvt.u32.u64 %0, t; }" : "=r"(a) : "l"(p));
    return a;
}
__device__ __forceinline__ void cpbulk(uint32_t dst, const void* src, uint32_t bytes,
                                       uint32_t mbar) {
    asm volatile(
        "cp.async.bulk.shared::cluster.global.mbarrier::complete_tx::bytes [%0], [%1], %2, [%3];"
        :: "r"(dst), "l"(src), "r"(bytes), "r"(mbar) : "memory");
}
#define MBAR_INIT(mb, n) \
    asm volatile("mbarrier.init.shared.b64 [%0], %1;" :: "r"(mb), "r"((uint32_t)(n)) : "memory")
#define MBAR_EXPECT(mb, n) \
    asm volatile("mbarrier.arrive.expect_tx.shared.b64 _, [%0], %1;" :: "r"(mb), "r"((uint32_t)(n)) : "memory")

__device__ __forceinline__ void mbar_wait(uint32_t mb, uint32_t parity) {
    uint32_t done;
    asm volatile(
        "{\n\t.reg .pred p;\n\t"
        "mbarrier.try_wait.parity.acquire.cta.shared::cta.b64 p, [%1], %2;\n\t"
        "selp.b32 %0, 1, 0, p;\n\t}"
        : "=r"(done) : "r"(mb), "r"(parity) : "memory");
    if (!done) {
        asm volatile(
            "{\n\t.reg .pred P1;\n\t"
            "W0_%=:\n\t"
            "mbarrier.try_wait.parity.acquire.cta.shared::cta.b64 P1, [%0], %1, 0x989680;\n\t"
            "@P1 bra.uni W1_%=;\n\t"
            "bra.uni W0_%=;\n\t"
            "W1_%=:\n\t}"
            :: "r"(mb), "r"(parity) : "memory");
    }
}
__device__ __forceinline__ void ldsm4(uint32_t& r0, uint32_t& r1, uint32_t& r2, uint32_t& r3,
                                      uint32_t a) {
    asm volatile("ldmatrix.sync.aligned.m8n8.x4.shared.b16 {%0,%1,%2,%3}, [%4];"
                 : "=r"(r0), "=r"(r1), "=r"(r2), "=r"(r3) : "r"(a));
}
__device__ __forceinline__ void mma16816(float* c, const uint32_t* a, const uint32_t* b) {
    asm volatile(
        "mma.sync.aligned.m16n8k16.row.col.f32.f16.f16.f32 "
        "{%0,%1,%2,%3}, {%4,%5,%6,%7}, {%8,%9}, {%0,%1,%2,%3};"
        : "+f"(c[0]), "+f"(c[1]), "+f"(c[2]), "+f"(c[3])
        : "r"(a[0]), "r"(a[1]), "r"(a[2]), "r"(a[3]), "r"(b[0]), "r"(b[1]));
}
__device__ __forceinline__ uint32_t pkh2(float a, float b) {
    __half2 h = __floats2half2_rn(a, b);
    return *(uint32_t*)&h;
}
__device__ __forceinline__ uint32_t lane_off(int r, int c) {
    return (uint32_t)(r * 80 + (c >> 3) * 16 + (c & 7) * 2);
}

// ---------------- 3-stage bulk-fed GEMM body (phi/g projections) ----------------
// EPI 5: phi -> pgimg (col bias, split hi/lo) | 6: g -> pgimg (row bias)
template <int NCH, bool SPLIT, int EPI>
__device__ __forceinline__ void gemm_body(
    const char* __restrict__ Ab, const char* __restrict__ Bb,
    char* smraw, uint32_t mb0, int z, int by, int bx,
    const float* __restrict__ bias, char* __restrict__ outImg, int tid) {
    constexpr uint32_t REG = SPLIT ? 20480 : 10240;
    constexpr uint32_t STAGE = SPLIT ? 40960 : 20480;
    uint32_t sbase = smem_u32(smraw);
    int lane = tid & 31, w = tid >> 5;
    int wm = w >> 2, wn = w & 3;

    if (tid == 0) { MBAR_INIT(mb0, 1); MBAR_INIT(mb0 + 8, 1); MBAR_INIT(mb0 + 16, 1); }
    __syncthreads();

    auto issue = [&](int ch) {
        uint32_t st = sbase + (uint32_t)(ch % 3) * STAGE;
        uint32_t mb = mb0 + (uint32_t)(ch % 3) * 8;
        MBAR_EXPECT(mb, SPLIT ? 40960u : 20480u);
        if (SPLIT) {
            cpbulk(st, Ab + (size_t)ch * REG, 10240, mb);
            cpbulk(st + 20480, Ab + (size_t)ch * REG + 10240, 10240, mb);
            cpbulk(st + 10240, Bb + (size_t)ch * REG, 10240, mb);
            cpbulk(st + 30720, Bb + (size_t)ch * REG + 10240, 10240, mb);
        } else {
            cpbulk(st, Ab + (size_t)ch * REG, 10240, mb);
            cpbulk(st + 10240, Bb + (size_t)ch * REG, 10240, mb);
        }
    };
    if (tid == 0) { issue(0); issue(1); issue(2); }

    float acc[4][4][4];
#pragma unroll
    for (int i = 0; i < 4; i++)
#pragma unroll
        for (int j = 0; j < 4; j++)
#pragma unroll
            for (int e = 0; e < 4; e++) acc[i][j][e] = 0.f;

    for (int ch = 0; ch < NCH; ch++) {
        mbar_wait(mb0 + (uint32_t)(ch % 3) * 8, (uint32_t)((ch / 3) & 1));
        uint32_t sa = sbase + (uint32_t)(ch % 3) * STAGE;
        uint32_t sb = sa + 10240;
#pragma unroll
        for (int k16 = 0; k16 < 2; k16++) {
            uint32_t a[4][4], b[4][2];
            uint32_t coff = (uint32_t)(k16 * 32 + (lane >> 4) * 16);
#pragma unroll
            for (int mi = 0; mi < 4; mi++) {
                uint32_t ad = sa + (uint32_t)(wm * 64 + mi * 16 + (lane & 15)) * 80 + coff;
                ldsm4(a[mi][0], a[mi][1], a[mi][2], a[mi][3], ad);
            }
#pragma unroll
            for (int nh = 0; nh < 2; nh++) {
                uint32_t bd = sb + (uint32_t)(wn * 32 + nh * 16 + (lane & 15)) * 80 + coff;
                uint32_t r0, r1, r2, r3;
                ldsm4(r0, r1, r2, r3, bd);
                b[nh * 2 + 0][0] = r0; b[nh * 2 + 0][1] = r2;
                b[nh * 2 + 1][0] = r1; b[nh * 2 + 1][1] = r3;
            }
#pragma unroll
            for (int mi = 0; mi < 4; mi++)
#pragma unroll
                for (int ni = 0; ni < 4; ni++) mma16816(acc[mi][ni], a[mi], b[ni]);
            if (SPLIT) {
                uint32_t al[4][4], bl[4][2];
#pragma unroll
                for (int mi = 0; mi < 4; mi++) {
                    uint32_t ad = sa + 20480 + (uint32_t)(wm * 64 + mi * 16 + (lane & 15)) * 80 + coff;
                    ldsm4(al[mi][0], al[mi][1], al[mi][2], al[mi][3], ad);
                }
#pragma unroll
                for (int nh = 0; nh < 2; nh++) {
                    uint32_t bd = sa + 30720 + (uint32_t)(wn * 32 + nh * 16 + (lane & 15)) * 80 + coff;
                    uint32_t r0, r1, r2, r3;
                    ldsm4(r0, r1, r2, r3, bd);
                    bl[nh * 2 + 0][0] = r0; bl[nh * 2 + 0][1] = r2;
                    bl[nh * 2 + 1][0] = r1; bl[nh * 2 + 1][1] = r3;
                }
#pragma unroll
                for (int mi = 0; mi < 4; mi++)
#pragma unroll
                    for (int ni = 0; ni < 4; ni++) {
                        mma16816(acc[mi][ni], a[mi], bl[ni]);
                        mma16816(acc[mi][ni], al[mi], b[ni]);
                    }
            }
        }
        __syncthreads();
        if (tid == 0 && ch + 3 < NCH) issue(ch + 3);
    }

    int r = lane >> 2, cp2 = (lane & 3) * 2;
    int row0 = by * 128 + wm * 64;
    int col0 = bx * 128 + wn * 32;
#pragma unroll
    for (int mi = 0; mi < 4; mi++) {
#pragma unroll
        for (int h = 0; h < 2; h++) {
            int row = row0 + mi * 16 + h * 8 + r;
            float t = (EPI == 6) ? bias[row] : 0.f;
#pragma unroll
            for (int ni = 0; ni < 4; ni++) {
                int col = col0 + ni * 8 + cp2;
                float v0 = acc[mi][ni][h * 2 + 0];
                float v1 = acc[mi][ni][h * 2 + 1];
                if (EPI == 5) {
                    v0 += bias[col]; v1 += bias[col + 1];
                    __half h0 = __float2half_rn(v0), h1 = __float2half_rn(v1);
                    uint32_t hi = ((uint32_t)*(uint16_t*)&h1 << 16) | *(uint16_t*)&h0;
                    uint32_t lo = pkh2(v0 - __half2float(h0), v1 - __half2float(h1));
                    char* base = outImg + (size_t)(z * 16 + (row >> 6)) * 61440;
                    uint32_t off = (uint32_t)(col >> 5) * 5120 + lane_off(row & 63, col & 31);
                    *(uint32_t*)(base + off) = hi;
                    *(uint32_t*)(base + off + 20480) = lo;
                } else {
                    uint32_t hv = pkh2(v0 + t, v1 + t);
                    char* base = outImg + (size_t)(z * 16 + (col >> 6)) * 61440 + 40960;
                    uint32_t off = (uint32_t)((col >> 5) & 1) * 10240 + lane_off(row, col & 31);
                    *(uint32_t*)(base + off) = hv;
                }
            }
        }
    }
}

// ---------------- mid kernel: phi (blocks 0-63) + g (blocks 64-127) ----------------
__global__ void __launch_bounds__(256, 1) mid_kernel(const float* __restrict__ bph,
                                                     const float* __restrict__ bg) {
    extern __shared__ char sm[];
    __shared__ __align__(8) uint64_t s_mbar[3];
    int tid = threadIdx.x;
    uint32_t mb0 = smem_u32(&s_mbar[0]);
    if (blockIdx.x < 64) {
        int z = blockIdx.x >> 3, by = blockIdx.x & 7;
        const char* Ab = g_pqimg + (size_t)(z * 8 + by) * (8 * 20480);
        gemm_body<8, true, 5>(Ab, g_wphimg, sm, mb0, z, by, 0, bph, g_pgimg, tid);
    } else {
        int i = blockIdx.x - 64;
        int z = i >> 3, bx = i & 7;
        const char* Bb = g_pvimg + (size_t)(z * 8 + bx) * (8 * 10240);
        gemm_body<8, false, 6>(g_wgimg, Bb, sm, mb0, z, 0, bx, bg, g_pgimg, tid);
    }
}

// ---------------- fused flash: theta prologue + S-softmax-y + final Ww GEMM + BN + resid ----------------
__global__ void __launch_bounds__(256, 1) flash_kernel(const float* __restrict__ bth,
                                                       const float* __restrict__ vres,
                                                       float* __restrict__ out) {
    extern __shared__ char sm[];
    __shared__ __align__(8) uint64_t s_mbar[3];
    uint32_t sbase = smem_u32(sm);
    uint32_t mb0 = smem_u32(&s_mbar[0]);
    const uint32_t STGSZ = 61440;

    int tid = threadIdx.x, lane = tid & 31, w = tid >> 5;
    int b = blockIdx.y;
    int nt = blockIdx.x;
    const char* kimgT = g_kimg + (size_t)(b * 32 + nt) * 8 * 20480;
    const char* pgB = g_pgimg + (size_t)b * 16 * 61440;

    if (tid == 0) { MBAR_INIT(mb0, 1); MBAR_INIT(mb0 + 8, 1); MBAR_INIT(mb0 + 16, 1); }
    __syncthreads();

    // chunk counter t: 0..7 prologue (k+Wth), 8..23 main (phi+g)
    auto issue = [&](int t) {
        uint32_t st = sbase + (uint32_t)(t % 3) * STGSZ;
        uint32_t mb = mb0 + (uint32_t)(t % 3) * 8;
        if (t < 8) {
            MBAR_EXPECT(mb, 40960u);
            cpbulk(st, kimgT + (size_t)t * 20480, 20480, mb);
            cpbulk(st + 20480, g_wthimg + (size_t)t * 20480, 20480, mb);
        } else {
            MBAR_EXPECT(mb, 61440u);
            cpbulk(st, pgB + (size_t)(t - 8) * 61440, 61440, mb);
        }
    };
    if (tid == 0) { issue(0); issue(1); issue(2); }

    // ======== PROLOGUE: theta = kT.Wth^T (3-pass split) ========
    float acc[16][4];
#pragma unroll
    for (int j = 0; j < 16; j++)
#pragma unroll
        for (int e = 0; e < 4; e++) acc[j][e] = 0.f;

    for (int ch = 0; ch < 8; ch++) {
        mbar_wait(mb0 + (uint32_t)(ch % 3) * 8, (uint32_t)((ch / 3) & 1));
        uint32_t st = sbase + (uint32_t)(ch % 3) * STGSZ;
#pragma unroll
        for (int k16 = 0; k16 < 2; k16++) {
            uint32_t coff = (uint32_t)(k16 * 32 + (lane >> 4) * 16);
            uint32_t arow = (uint32_t)(w * 16 + (lane & 15)) * 80;
            uint32_t ah[4], al[4];
            ldsm4(ah[0], ah[1], ah[2], ah[3], st + arow + coff);
            ldsm4(al[0], al[1], al[2], al[3], st + 10240 + arow + coff);
#pragma unroll
            for (int nh = 0; nh < 8; nh++) {
                uint32_t brow = (uint32_t)(nh * 16 + (lane & 15)) * 80;
                uint32_t r0, r1, r2, r3;
                uint32_t bh0[2], bh1[2], bl0[2], bl1[2];
                ldsm4(r0, r1, r2, r3, st + 20480 + brow + coff);
                bh0[0] = r0; bh0[1] = r2; bh1[0] = r1; bh1[1] = r3;
                ldsm4(r0, r1, r2, r3, st + 30720 + brow + coff);
                bl0[0] = r0; bl0[1] = r2; bl1[0] = r1; bl1[1] = r3;
                mma16816(acc[2 * nh], ah, bh0);
                mma16816(acc[2 * nh + 1], ah, bh1);
                mma16816(acc[2 * nh], ah, bl0);
                mma16816(acc[2 * nh + 1], ah, bl1);
                mma16816(acc[2 * nh], al, bh0);
                mma16816(acc[2 * nh + 1], al, bh1);
            }
        }
        __syncthreads();
        if (tid == 0) issue(ch + 3);
    }

    // bias + hi/lo split -> A-fragments
    uint32_t th_hi[8][4], th_lo[8][4];
    {
        int t2 = (lane & 3) * 2;
#pragma unroll
        for (int s = 0; s < 8; s++) {
#pragma unroll
            for (int hf = 0; hf < 2; hf++) {
                int nb = 2 * s + hf;
                float b0 = bth[8 * nb + t2], b1 = bth[8 * nb + t2 + 1];
                float x0 = acc[nb][0] + b0, x1 = acc[nb][1] + b1;
                float x2 = acc[nb][2] + b0, x3 = acc[nb][3] + b1;
                __half hx0 = __float2half_rn(x0), hx1 = __float2half_rn(x1);
                __half hx2 = __float2half_rn(x2), hx3 = __float2half_rn(x3);
                th_hi[s][2 * hf + 0] = ((uint32_t)*(uint16_t*)&hx1 << 16) | *(uint16_t*)&hx0;
                th_hi[s][2 * hf + 1] = ((uint32_t)*(uint16_t*)&hx3 << 16) | *(uint16_t*)&hx2;
                th_lo[s][2 * hf + 0] = pkh2(x0 - __half2float(hx0), x1 - __half2float(hx1));
                th_lo[s][2 * hf + 1] = pkh2(x2 - __half2float(hx2), x3 - __half2float(hx3));
            }
        }
    }

    // ======== MAIN LOOP: S -> online softmax -> y ========
    float yacc[16][4];
#pragma unroll
    for (int j = 0; j < 16; j++)
#pragma unroll
        for (int e = 0; e < 4; e++) yacc[j][e] = 0.f;
    float rmax0 = -1e30f, rmax1 = -1e30f, rsum0 = 0.f, rsum1 = 0.f;

    for (int mt = 0; mt < 16; mt++) {
        int t = 8 + mt;
        mbar_wait(mb0 + (uint32_t)(t % 3) * 8, (uint32_t)((t / 3) & 1));
        uint32_t st = sbase + (uint32_t)(t % 3) * STGSZ;

        float sacc[8][4];
#pragma unroll
        for (int j = 0; j < 8; j++)
#pragma unroll
            for (int e = 0; e < 4; e++) sacc[j][e] = 0.f;

#pragma unroll
        for (int s = 0; s < 8; s++) {
            uint32_t chunk = (uint32_t)(s >> 1);
            uint32_t inner = (uint32_t)((s & 1) * 32 + (lane >> 4) * 16);
#pragma unroll
            for (int p = 0; p < 4; p++) {
                uint32_t brow = (uint32_t)(p * 16 + (lane & 15)) * 80;
                uint32_t bad = st + chunk * 5120 + brow + inner;
                uint32_t r0, r1, r2, r3;
                uint32_t bh0[2], bh1[2], bl0[2], bl1[2];
                ldsm4(r0, r1, r2, r3, bad);
                bh0[0] = r0; bh0[1] = r2; bh1[0] = r1; bh1[1] = r3;
                ldsm4(r0, r1, r2, r3, bad + 20480);
                bl0[0] = r0; bl0[1] = r2; bl1[0] = r1; bl1[1] = r3;
                mma16816(sacc[2 * p], th_hi[s], bh0);
                mma16816(sacc[2 * p + 1], th_hi[s], bh1);
                mma16816(sacc[2 * p], th_hi[s], bl0);
                mma16816(sacc[2 * p + 1], th_hi[s], bl1);
                mma16816(sacc[2 * p], th_lo[s], bh0);
                mma16816(sacc[2 * p + 1], th_lo[s], bh1);
            }
        }

        float tm0 = -1e30f, tm1 = -1e30f;
#pragma unroll
        for (int j = 0; j < 8; j++) {
            tm0 = fmaxf(tm0, fmaxf(sacc[j][0], sacc[j][1]));
            tm1 = fmaxf(tm1, fmaxf(sacc[j][2], sacc[j][3]));
        }
        tm0 = fmaxf(tm0, __shfl_xor_sync(0xffffffffu, tm0, 1));
        tm0 = fmaxf(tm0, __shfl_xor_sync(0xffffffffu, tm0, 2));
        tm1 = fmaxf(tm1, __shfl_xor_sync(0xffffffffu, tm1, 1));
        tm1 = fmaxf(tm1, __shfl_xor_sync(0xffffffffu, tm1, 2));
        float mn0 = fmaxf(rmax0, tm0), mn1 = fmaxf(rmax1, tm1);
        float sc0 = __expf(rmax0 - mn0), sc1 = __expf(rmax1 - mn1);
        float ts0 = 0.f, ts1 = 0.f;
#pragma unroll
        for (int j = 0; j < 8; j++) {
            sacc[j][0] = __expf(sacc[j][0] - mn0);
            sacc[j][1] = __expf(sacc[j][1] - mn0);
            sacc[j][2] = __expf(sacc[j][2] - mn1);
            sacc[j][3] = __expf(sacc[j][3] - mn1);
            ts0 += sacc[j][0] + sacc[j][1];
            ts1 += sacc[j][2] + sacc[j][3];
        }
        ts0 += __shfl_xor_sync(0xffffffffu, ts0, 1);
        ts0 += __shfl_xor_sync(0xffffffffu, ts0, 2);
        ts1 += __shfl_xor_sync(0xffffffffu, ts1, 1);
        ts1 += __shfl_xor_sync(0xffffffffu, ts1, 2);
        rsum0 = rsum0 * sc0 + ts0;
        rsum1 = rsum1 * sc1 + ts1;
        rmax0 = mn0; rmax1 = mn1;
#pragma unroll
        for (int j = 0; j < 16; j++) {
            yacc[j][0] *= sc0; yacc[j][1] *= sc0;
            yacc[j][2] *= sc1; yacc[j][3] *= sc1;
        }

        uint32_t pf[4][4];
#pragma unroll
        for (int s2 = 0; s2 < 4; s2++) {
            pf[s2][0] = pkh2(sacc[2 * s2][0], sacc[2 * s2][1]);
            pf[s2][1] = pkh2(sacc[2 * s2][2], sacc[2 * s2][3]);
            pf[s2][2] = pkh2(sacc[2 * s2 + 1][0], sacc[2 * s2 + 1][1]);
            pf[s2][3] = pkh2(sacc[2 * s2 + 1][2], sacc[2 * s2 + 1][3]);
        }

#pragma unroll
        for (int s2 = 0; s2 < 4; s2++) {
            uint32_t chunk = (uint32_t)(s2 >> 1);
            uint32_t inner = (uint32_t)((s2 & 1) * 32 + (lane >> 4) * 16);
#pragma unroll
            for (int pc = 0; pc < 8; pc++) {
                uint32_t brow = (uint32_t)(pc * 16 + (lane & 15)) * 80;
                uint32_t r0, r1, r2, r3;
                ldsm4(r0, r1, r2, r3, st + 40960 + chunk * 10240 + brow + inner);
                uint32_t bb0[2] = {r0, r2};
                uint32_t bb1[2] = {r1, r3};
                mma16816(yacc[2 * pc], pf[s2], bb0);
                mma16816(yacc[2 * pc + 1], pf[s2], bb1);
            }
        }
        __syncthreads();
        if (tid == 0 && t + 3 < 24) issue(t + 3);
    }

    // ======== EPILOGUE: pack y into B-frags, final out = BN(Ww.y^T) + v ========
    // C-frag -> B-frag identity: B{n=l>>2, k=(l&3)*2} == C{row=l>>2, col=(l&3)*2}.
    float inv0 = 1.f / rsum0, inv1 = 1.f / rsum1;
    uint32_t yB[8][2][2];
#pragma unroll
    for (int s = 0; s < 8; s++) {
        yB[s][0][0] = pkh2(yacc[2 * s][0] * inv0, yacc[2 * s][1] * inv0);
        yB[s][0][1] = pkh2(yacc[2 * s + 1][0] * inv0, yacc[2 * s + 1][1] * inv0);
        yB[s][1][0] = pkh2(yacc[2 * s][2] * inv1, yacc[2 * s][3] * inv1);
        yB[s][1][1] = pkh2(yacc[2 * s + 1][2] * inv1, yacc[2 * s + 1][3] * inv1);
    }

    // pull full Ww image (80KB) into the now-free stage smem; 9th completion on slot0 -> parity 0
    if (tid == 0) {
        MBAR_EXPECT(mb0, 81920u);
        cpbulk(sbase, g_wwimg, 81920, mb0);
    }
    mbar_wait(mb0, 0u);

    int r = lane >> 2, c2 = (lane & 3) * 2;
    int nbase = nt * 128 + w * 16;
#pragma unroll
    for (int coh = 0; coh < 2; coh++) {
        float oacc[8][2][4];
#pragma unroll
        for (int ct = 0; ct < 8; ct++)
#pragma unroll
            for (int nf = 0; nf < 2; nf++)
#pragma unroll
                for (int e = 0; e < 4; e++) oacc[ct][nf][e] = 0.f;

#pragma unroll
        for (int s = 0; s < 8; s++) {
            uint32_t coff = (uint32_t)((s & 1) * 32 + (lane >> 4) * 16);
            uint32_t rbase = sbase + (uint32_t)(coh * 4 + (s >> 1)) * 10240;
#pragma unroll
            for (int ct = 0; ct < 8; ct++) {
                uint32_t a[4];
                ldsm4(a[0], a[1], a[2], a[3],
                      rbase + (uint32_t)(ct * 16 + (lane & 15)) * 80 + coff);
                mma16816(oacc[ct][0], a, yB[s][0]);
                mma16816(oacc[ct][1], a, yB[s][1]);
            }
        }

        // write: out[z][co][n] = oacc*bns[co] + bnt[co] + v[z][co][n]
#pragma unroll
        for (int ct = 0; ct < 8; ct++) {
#pragma unroll
            for (int h = 0; h < 2; h++) {
                int co = coh * 128 + ct * 16 + h * 8 + r;
                float s1 = g_bns[co], t1 = g_bnt[co];
                size_t rowb = (size_t)b * CC * NPIX + (size_t)co * NPIX;
#pragma unroll
                for (int nf = 0; nf < 2; nf++) {
                    int n = nbase + nf * 8 + c2;
                    float2 rr = *(const float2*)(vres + rowb + n);
                    float v0 = oacc[ct][nf][h * 2 + 0] * s1 + t1 + rr.x;
                    float v1 = oacc[ct][nf][h * 2 + 1] * s1 + t1 + rr.y;
                    *(float2*)(out + rowb + n) = make_float2(v0, v1);
                }
            }
        }
    }
}

// ---------------- merged prep: pooltrans (0..4095) + transk (4096..12287) + wprep ----------------
__global__ void __launch_bounds__(256) prep_kernel(
    const float* __restrict__ q, const float* __restrict__ v, const float* __restrict__ k,
    const float* __restrict__ Wth, const float* __restrict__ Wph,
    const float* __restrict__ Wg, const float* __restrict__ Ww,
    const float* __restrict__ gamma, const float* __restrict__ beta,
    const float* __restrict__ mean, const float* __restrict__ var,
    const float* __restrict__ bw) {
    __shared__ float ts[32][33];
    int bid = blockIdx.x;
    int tid = threadIdx.x;
    int tx = tid & 31, ty = tid >> 5;

    if (bid < 4096) {
        int z = bid >> 8, rem = bid & 255;
        int m0 = (rem & 31) * 32, c0 = (rem >> 5) * 32;
        bool isq = (z < BB);
        const float* src = isq ? q : v;
        int b = z & (BB - 1);
        const float* sb = src + (size_t)b * CC * NPIX;
        int m = m0 + tx, mi = m >> 5, mj = m & 31;
#pragma unroll
        for (int i = 0; i < 4; i++) {
            int c = c0 + ty + i * 8;
            const float* p = sb + (size_t)c * NPIX + (2 * mi) * WW + 2 * mj;
            ts[ty + i * 8][tx] = 0.25f * (p[0] + p[1] + p[WW] + p[WW + 1]);
        }
        __syncthreads();
        int ch = c0 >> 5;
#pragma unroll
        for (int i = 0; i < 4; i++) {
            float val = ts[tx][ty + i * 8];
            int mm = m0 + ty + i * 8;
            int mtile = mm >> 7, r = mm & 127;
            uint32_t off = lane_off(r, tx);
            __half h = __float2half_rn(val);
            if (isq) {
                char* base = g_pqimg + (size_t)((b * 8 + mtile) * 8 + ch) * 20480;
                *(__half*)(base + off) = h;
                *(__half*)(base + 10240 + off) = __float2half_rn(val - __half2float(h));
            } else {
                *(__half*)(g_pvimg + (size_t)((b * 8 + mtile) * 8 + ch) * 10240 + off) = h;
            }
        }
    } else if (bid < 12288) {
        int i = bid - 4096;
        int b = i >> 10;
        int n0 = (i & 127) * 32, c0 = ((i >> 7) & 7) * 32;
        const float* sb = k + (size_t)b * CC * NPIX;
#pragma unroll
        for (int j = 0; j < 4; j++)
            ts[ty + j * 8][tx] = sb[(size_t)(c0 + ty + j * 8) * NPIX + n0 + tx];
        __syncthreads();
        int ch = c0 >> 5;
#pragma unroll
        for (int j = 0; j < 4; j++) {
            float val = ts[tx][ty + j * 8];
            int nn = n0 + ty + j * 8;
            int nt = nn >> 7, r = nn & 127;
            uint32_t off = lane_off(r, tx);
            char* base = g_kimg + (size_t)((b * 32 + nt) * 8 + ch) * 20480;
            __half h = __float2half_rn(val);
            *(__half*)(base + off) = h;
            *(__half*)(base + 10240 + off) = __float2half_rn(val - __half2float(h));
        }
    } else {
        int i = (bid - 12288) * 256 + tid;
        {
            int row = i >> 8, c = i & 255;
            int ch = c >> 5, cc = c & 31;
            uint32_t off = lane_off(row, cc);
            float a = Wth[i];
            __half h = __float2half_rn(a);
            *(__half*)(g_wthimg + ch * 20480 + off) = h;
            *(__half*)(g_wthimg + ch * 20480 + 10240 + off) = __float2half_rn(a - __half2float(h));
            float p = Wph[i];
            __half hp = __float2half_rn(p);
            *(__half*)(g_wphimg + ch * 20480 + off) = hp;
            *(__half*)(g_wphimg + ch * 20480 + 10240 + off) = __float2half_rn(p - __half2float(hp));
            *(__half*)(g_wgimg + ch * 10240 + off) = __float2half_rn(Wg[i]);
        }
        {
            int row = i >> 7, ci = i & 127;
            int rt = row >> 7, rr = row & 127;
            int ch = ci >> 5, cc = ci & 31;
            *(__half*)(g_wwimg + (rt * 4 + ch) * 10240 + lane_off(rr, cc)) = __float2half_rn(Ww[i]);
        }
        if (i < CC) {
            float sc = gamma[i] * rsqrtf(var[i] + 1e-5f);
            g_bns[i] = sc;
            g_bnt[i] = beta[i] + (bw[i] - mean[i]) * sc;
        }
    }
}

// ---------------- launch ----------------
extern "C" void kernel_launch(void* const* d_in, const int* in_sizes, int n_in,
                              void* d_out, int out_size) {
    (void)in_sizes; (void)n_in; (void)out_size;
    const float* q     = (const float*)d_in[0];
    const float* k     = (const float*)d_in[1];
    const float* v     = (const float*)d_in[2];
    const float* Wg    = (const float*)d_in[3];
    const float* bg    = (const float*)d_in[4];
    const float* Wth   = (const float*)d_in[5];
    const float* bth   = (const float*)d_in[6];
    const float* Wph   = (const float*)d_in[7];
    const float* bph   = (const float*)d_in[8];
    const float* Ww    = (const float*)d_in[9];
    const float* bw    = (const float*)d_in[10];
    const float* gamma = (const float*)d_in[11];
    const float* beta  = (const float*)d_in[12];
    const float* mean  = (const float*)d_in[13];
    const float* var   = (const float*)d_in[14];
    float* out = (float*)d_out;

    const int SMM = 122880;  // mid: 3 x 40960
    const int SMF = 184320;  // flash: 3 x 61440 (Ww 81920 reuses stages post-loop)
    cudaFuncSetAttribute(mid_kernel, cudaFuncAttributeMaxDynamicSharedMemorySize, SMM);
    cudaFuncSetAttribute(flash_kernel, cudaFuncAttributeMaxDynamicSharedMemorySize, SMF);

    // 1) merged prep -> images
    prep_kernel<<<12416, 256>>>(q, v, k, Wth, Wph, Wg, Ww, gamma, beta, mean, var, bw);
    // 2) phi + g projections
    mid_kernel<<<128, 256, SMM>>>(bph, bg);
    // 3) fused: theta prologue + flash attention + final GEMM + BN + residual
    flash_kernel<<<dim3(NPIX / 128, BB), 256, SMF>>>(bth, v, out);
}